// round 7
// baseline (speedup 1.0000x reference)
#include <cuda_runtime.h>
#include <cuda_bf16.h>
#include <math.h>
#include <stdint.h>

// Problem constants
#define D64   64
#define HH    2
#define HD    128
#define LL    3
#define NN    50000
#define GG    128
#define EE    600000
#define NE_   300000
#define NAUG  (NN + GG)          // 50128
#define M0    (EE + 2 * NN)      // 700000
#define MM    (M0 + NAUG)        // 750128
#define TAILR (MM - EE)          // 150128
#define NB_SCAN ((NAUG + 255) / 256)   // 196

#define CDIV(a, b) (((a) + (b) - 1) / (b))

// ---------------- device scratch (static, no allocs) ----------------
__device__ int    g_src[MM];
__device__ int    g_dst[MM];
__device__ int    g_deg[NAUG];
__device__ int    g_rowptr[NAUG + 1];
__device__ int    g_bsum[256];
__device__ int    g_fill[NAUG];
__device__ int    g_esrc[MM];
__device__ int    g_eid[MM];
__device__ float  g_eperm[(size_t)MM * D64];     // e_aug rows in CSR order
__device__ float  g_tail[(size_t)TAILR * D64];   // e_aug rows >= EE
__device__ float  g_h[NAUG * D64];
__device__ float  g_hn[NAUG * D64];
__device__ float  g_agg[NAUG * D64];
__device__ float  g_big[(size_t)NAUG * 384];     // [cat(128) | t(128) | we(128)]
__device__ float  g_qkvp[(size_t)NAUG * 512];    // [q | k | v | qp]
__device__ float  g_lh[NAUG * D64];
__device__ float  g_ln2[NAUG * D64];
__device__ float  g_ffh[(size_t)NAUG * 256];
__device__ float  g_w2[HD * HD];
__device__ float  g_w3[HD * HD];
__device__ float  g_qpw[HD * HD];
__device__ float  g_swlw[HD * D64];
__device__ float  g_lw3[HD * D64];
__device__ float  g_wcat[HD * 512];
__device__ float  g_bcat[512];
__device__ float  g_wlin[384 * D64];
__device__ float  g_blb[D64];
__device__ float  g_cntn[GG];
__device__ double g_lsum[GG];
__device__ double g_lsumsq[GG];
__device__ float  g_mean[GG];
__device__ float  g_rstd[GG];
__device__ int    g_abatch[NAUG];
__device__ float  g_gsum[GG * D64];

// ---------------- setup kernels ----------------
__global__ void k_build_edges(const int* __restrict__ ei0, const int* __restrict__ ei1,
                              const int* __restrict__ batch) {
    int m = blockIdx.x * blockDim.x + threadIdx.x;
    if (m >= MM) return;
    int s, d;
    if (m < EE)               { s = ei0[m]; d = ei1[m]; }
    else if (m < EE + NN)     { int i = m - EE;          s = i;             d = batch[i] + NN; }
    else if (m < EE + 2 * NN) { int i = m - EE - NN;     s = batch[i] + NN; d = i; }
    else                      { int i = m - EE - 2 * NN; s = i;             d = i; }
    g_src[m] = s; g_dst[m] = d;
    atomicAdd(&g_deg[d], 1);
}

__global__ void k_scanA() {
    __shared__ int sh[256];
    int t = threadIdx.x;
    int i = blockIdx.x * 256 + t;
    int v = (i < NAUG) ? g_deg[i] : 0;
    sh[t] = v;
    __syncthreads();
    for (int off = 1; off < 256; off <<= 1) {
        int a = (t >= off) ? sh[t - off] : 0;
        __syncthreads();
        sh[t] += a;
        __syncthreads();
    }
    if (i < NAUG) g_rowptr[i] = sh[t] - v;
    if (t == 255) g_bsum[blockIdx.x] = sh[255];
}

__global__ void k_scanB() {
    __shared__ int sh[256];
    int t = threadIdx.x;
    int v = (t < NB_SCAN) ? g_bsum[t] : 0;
    sh[t] = v;
    __syncthreads();
    for (int off = 1; off < 256; off <<= 1) {
        int a = (t >= off) ? sh[t - off] : 0;
        __syncthreads();
        sh[t] += a;
        __syncthreads();
    }
    if (t < NB_SCAN) g_bsum[t] = sh[t] - v;
}

__global__ void k_scanC() {
    int i = blockIdx.x * 256 + threadIdx.x;
    if (i < NAUG) {
        int r = g_rowptr[i] + g_bsum[i >> 8];
        g_rowptr[i] = r;
        g_fill[i] = r;
        g_deg[i] = 0;                 // self-clean
    }
    if (i == 0) g_rowptr[NAUG] = MM;
}

__global__ void k_scatter() {
    int m = blockIdx.x * blockDim.x + threadIdx.x;
    if (m >= MM) return;
    int pos = atomicAdd(&g_fill[g_dst[m]], 1);
    g_esrc[pos] = g_src[m];
    g_eid[pos]  = m;
}

__global__ void k_abatch(const int* __restrict__ batch) {
    int i = blockIdx.x * blockDim.x + threadIdx.x;
    if (i >= NAUG) return;
    g_abatch[i] = (i < NN) ? batch[i] : (i - NN);
}

__global__ void k_cntn(const int* __restrict__ batch) {
    int i = blockIdx.x * blockDim.x + threadIdx.x;
    if (i >= NN) return;
    atomicAdd(&g_cntn[batch[i]], 1.f);
}

__global__ void k_init_h(const float* __restrict__ x, const float* __restrict__ cond) {
    int idx = blockIdx.x * blockDim.x + threadIdx.x;
    if (idx >= NAUG * D64) return;
    g_h[idx] = (idx < NN * D64) ? x[idx] : cond[idx - NN * D64];
}

__global__ void k_tail_ep() {
    int idx = blockIdx.x * blockDim.x + threadIdx.x;
    if (idx >= 2 * NN * D64) return;
    g_tail[idx] = ((idx & 63) == 0) ? 1.f : 0.f;
}

__global__ void k_tail_csr(const float* __restrict__ edge_attr) {
    int i = (blockIdx.x * blockDim.x + threadIdx.x) >> 5;
    int lane = threadIdx.x & 31;
    if (i >= NAUG) return;
    float2 acc = {0.f, 0.f};
    float cnt = 0.f;
    int e0 = g_rowptr[i], e1 = g_rowptr[i + 1];
    for (int e = e0; e < e1; e++) {
        int m = g_eid[e];
        if (m < EE) {
            float2 ev = ((const float2*)(edge_attr + (size_t)m * D64))[lane];
            acc.x += ev.x; acc.y += ev.y;
            cnt += 1.f;
        } else if (m < M0) {
            if (lane == 0) acc.x += 1.f;
            cnt += 1.f;
        }
    }
    float invc = 1.f / fmaxf(cnt, 1.f);
    float2 o = {acc.x * invc, acc.y * invc};
    ((float2*)(g_tail + (size_t)(2 * NN + i) * D64))[lane] = o;
}

// permute e_aug rows into CSR order (sequential reads for all later edge sweeps)
__global__ void k_eperm(const float* __restrict__ edge_attr) {
    int gw = (blockIdx.x * blockDim.x + threadIdx.x) >> 5;
    int lane = threadIdx.x & 31;
    if (gw >= MM) return;
    int m = g_eid[gw];
    const float* ep = (m < EE) ? edge_attr + (size_t)m * D64
                               : g_tail + (size_t)(m - EE) * D64;
    float2 v = ((const float2*)ep)[lane];
    ((float2*)(g_eperm + (size_t)gw * D64))[lane] = v;
}

// ---------------- graph layernorm ----------------
__global__ void k_ln_stats(const float* __restrict__ X) {
    int i = (blockIdx.x * blockDim.x + threadIdx.x) >> 5;
    int lane = threadIdx.x & 31;
    if (i >= NAUG) return;
    float2 v = ((const float2*)(X + (size_t)i * D64))[lane];
    float s  = v.x + v.y;
    float ss = v.x * v.x + v.y * v.y;
#pragma unroll
    for (int off = 16; off; off >>= 1) {
        s  += __shfl_xor_sync(0xffffffffu, s, off);
        ss += __shfl_xor_sync(0xffffffffu, ss, off);
    }
    if (lane == 0) {
        int b = g_abatch[i];
        atomicAdd(&g_lsum[b], (double)s);
        atomicAdd(&g_lsumsq[b], (double)ss);
    }
}

__global__ void k_ln_final() {
    int g = threadIdx.x;
    if (g >= GG) return;
    double norm = (double)fmaxf(g_cntn[g] + 1.f, 1.f) * D64;
    double mean = g_lsum[g] / norm;
    double var  = g_lsumsq[g] / norm - mean * mean;
    g_mean[g] = (float)mean;
    g_rstd[g] = rsqrtf((float)var + 1e-5f);
    g_lsum[g] = 0.0;            // self-clean
    g_lsumsq[g] = 0.0;
}

// writes hn AND big[:, 0:64] (cat left half)
__global__ void k_ln_apply2(const float* __restrict__ X) {
    int idx = blockIdx.x * blockDim.x + threadIdx.x;
    if (idx >= NAUG * D64) return;
    int i = idx >> 6, d = idx & 63;
    int b = g_abatch[i];
    float v = (X[idx] - g_mean[b]) * g_rstd[b];
    g_hn[idx] = v;
    g_big[(size_t)i * 384 + d] = v;
}

__global__ void k_ln_apply(const float* __restrict__ X, float* __restrict__ Y) {
    int idx = blockIdx.x * blockDim.x + threadIdx.x;
    if (idx >= NAUG * D64) return;
    int b = g_abatch[idx >> 6];
    Y[idx] = (X[idx] - g_mean[b]) * g_rstd[b];
}

// ---------------- gen_conv: regular nodes (warp each), e sequential ----------------
__global__ void k_gen() {
    int i = (blockIdx.x * blockDim.x + threadIdx.x) >> 5;
    int lane = threadIdx.x & 31;
    if (i >= NN) return;
    float2 acc = {0.f, 0.f};
    int e0 = g_rowptr[i], e1 = g_rowptr[i + 1];
    for (int e = e0; e < e1; e++) {
        int s = g_esrc[e];
        float2 ev = ((const float2*)(g_eperm + (size_t)e * D64))[lane];
        float2 hv = ((const float2*)(g_hn + (size_t)s * D64))[lane];
        acc.x += fmaxf(hv.x + ev.x, 0.f) + 1e-7f;
        acc.y += fmaxf(hv.y + ev.y, 0.f) + 1e-7f;
    }
    float2 hi = ((const float2*)(g_hn + (size_t)i * D64))[lane];
    float2 o = {acc.x + hi.x, acc.y + hi.y};
    ((float2*)(g_agg + (size_t)i * D64))[lane] = o;
}

__global__ void k_gen_v() {
    __shared__ float sa[64];
    int i = NN + blockIdx.x;
    int tid = threadIdx.x, lane = tid & 31, wid = tid >> 5;
    if (tid < 64) sa[tid] = 0.f;
    __syncthreads();
    int e0 = g_rowptr[i], e1 = g_rowptr[i + 1];
    float2 acc = {0.f, 0.f};
    for (int e = e0 + wid; e < e1; e += 8) {
        int s = g_esrc[e];
        float2 ev = ((const float2*)(g_eperm + (size_t)e * D64))[lane];
        float2 hv = ((const float2*)(g_hn + (size_t)s * D64))[lane];
        acc.x += fmaxf(hv.x + ev.x, 0.f) + 1e-7f;
        acc.y += fmaxf(hv.y + ev.y, 0.f) + 1e-7f;
    }
    atomicAdd(&sa[2 * lane],     acc.x);
    atomicAdd(&sa[2 * lane + 1], acc.y);
    __syncthreads();
    if (tid < 64) g_agg[(size_t)i * D64 + tid] = sa[tid] + g_hn[(size_t)i * D64 + tid];
}

// ---------------- fused single-pass attention (online softmax), e sequential ----------------
__global__ void k_attn() {
    int i = (blockIdx.x * blockDim.x + threadIdx.x) >> 5;
    int lane = threadIdx.x & 31;
    if (i >= NN) return;
    int el = lane & 15;
    float4 q4  = *(const float4*)(g_qkvp + (size_t)i * 512 + 4 * lane);
    float4 qp4 = *(const float4*)(g_qkvp + (size_t)i * 512 + 384 + 4 * lane);
    int e0 = g_rowptr[i], e1 = g_rowptr[i + 1];
    float mx = -INFINITY, sum = 0.f;
    float4 vacc = {0.f, 0.f, 0.f, 0.f};
    float4 eacc = {0.f, 0.f, 0.f, 0.f};
    for (int e = e0; e < e1; e++) {
        int s = g_esrc[e];
        const float* ep = g_eperm + (size_t)e * D64;
        float4 k4 = *(const float4*)(g_qkvp + (size_t)s * 512 + 128 + 4 * lane);
        float4 e4 = *(const float4*)(ep + 4 * el);
        float p = q4.x * k4.x + q4.y * k4.y + q4.z * k4.z + q4.w * k4.w
                + qp4.x * e4.x + qp4.y * e4.y + qp4.z * e4.z + qp4.w * e4.w;
        p += __shfl_xor_sync(0xffffffffu, p, 1);
        p += __shfl_xor_sync(0xffffffffu, p, 2);
        p += __shfl_xor_sync(0xffffffffu, p, 4);
        p += __shfl_xor_sync(0xffffffffu, p, 8);
        float a = p * 0.125f;
        if (a > mx) {
            float sc = expf(mx - a);
            sum *= sc;
            vacc.x *= sc; vacc.y *= sc; vacc.z *= sc; vacc.w *= sc;
            eacc.x *= sc; eacc.y *= sc; eacc.z *= sc; eacc.w *= sc;
            mx = a;
        }
        float w = expf(a - mx);
        sum += w;
        float4 v4 = *(const float4*)(g_qkvp + (size_t)s * 512 + 256 + 4 * lane);
        vacc.x += w * v4.x; vacc.y += w * v4.y; vacc.z += w * v4.z; vacc.w += w * v4.w;
        eacc.x += w * e4.x; eacc.y += w * e4.y; eacc.z += w * e4.z; eacc.w += w * e4.w;
    }
    float inv = 1.f / (sum + 1e-16f);
    float4 to = {vacc.x * inv, vacc.y * inv, vacc.z * inv, vacc.w * inv};
    float4 wo = {eacc.x * inv, eacc.y * inv, eacc.z * inv, eacc.w * inv};
    *(float4*)(g_big + (size_t)i * 384 + 128 + 4 * lane) = to;
    *(float4*)(g_big + (size_t)i * 384 + 256 + 4 * lane) = wo;
}

__global__ void k_attn_v() {
    __shared__ float sv[128];
    __shared__ float se[128];
    __shared__ float ssg[2];
    __shared__ float swmx[16];
    __shared__ float gmx[2];
    int i = NN + blockIdx.x;
    int tid = threadIdx.x, lane = tid & 31, wid = tid >> 5;
    int el = lane & 15;
    int hh = lane >> 4;
    if (tid < 128) { sv[tid] = 0.f; se[tid] = 0.f; }
    if (tid < 2) ssg[tid] = 0.f;
    __syncthreads();
    float4 q4  = *(const float4*)(g_qkvp + (size_t)i * 512 + 4 * lane);
    float4 qp4 = *(const float4*)(g_qkvp + (size_t)i * 512 + 384 + 4 * lane);
    int e0 = g_rowptr[i], e1 = g_rowptr[i + 1];
    float mx = -INFINITY, sum = 0.f;
    float4 vacc = {0.f, 0.f, 0.f, 0.f};
    float4 eacc = {0.f, 0.f, 0.f, 0.f};
    for (int e = e0 + wid; e < e1; e += 8) {
        int s = g_esrc[e];
        const float* ep = g_eperm + (size_t)e * D64;
        float4 k4 = *(const float4*)(g_qkvp + (size_t)s * 512 + 128 + 4 * lane);
        float4 e4 = *(const float4*)(ep + 4 * el);
        float p = q4.x * k4.x + q4.y * k4.y + q4.z * k4.z + q4.w * k4.w
                + qp4.x * e4.x + qp4.y * e4.y + qp4.z * e4.z + qp4.w * e4.w;
        p += __shfl_xor_sync(0xffffffffu, p, 1);
        p += __shfl_xor_sync(0xffffffffu, p, 2);
        p += __shfl_xor_sync(0xffffffffu, p, 4);
        p += __shfl_xor_sync(0xffffffffu, p, 8);
        float a = p * 0.125f;
        if (a > mx) {
            float sc = expf(mx - a);
            sum *= sc;
            vacc.x *= sc; vacc.y *= sc; vacc.z *= sc; vacc.w *= sc;
            eacc.x *= sc; eacc.y *= sc; eacc.z *= sc; eacc.w *= sc;
            mx = a;
        }
        float w = expf(a - mx);
        sum += w;
        float4 v4 = *(const float4*)(g_qkvp + (size_t)s * 512 + 256 + 4 * lane);
        vacc.x += w * v4.x; vacc.y += w * v4.y; vacc.z += w * v4.z; vacc.w += w * v4.w;
        eacc.x += w * e4.x; eacc.y += w * e4.y; eacc.z += w * e4.z; eacc.w += w * e4.w;
    }
    if (el == 0) swmx[wid * 2 + hh] = mx;
    __syncthreads();
    if (tid < 2) {
        float m = -INFINITY;
#pragma unroll
        for (int w = 0; w < 8; w++) m = fmaxf(m, swmx[w * 2 + tid]);
        gmx[tid] = m;
    }
    __syncthreads();
    float sc = expf(mx - gmx[hh]);
    atomicAdd(&sv[4 * lane],     vacc.x * sc); atomicAdd(&sv[4 * lane + 1], vacc.y * sc);
    atomicAdd(&sv[4 * lane + 2], vacc.z * sc); atomicAdd(&sv[4 * lane + 3], vacc.w * sc);
    atomicAdd(&se[4 * lane],     eacc.x * sc); atomicAdd(&se[4 * lane + 1], eacc.y * sc);
    atomicAdd(&se[4 * lane + 2], eacc.z * sc); atomicAdd(&se[4 * lane + 3], eacc.w * sc);
    if (el == 0) atomicAdd(&ssg[hh], sum * sc);
    __syncthreads();
    if (tid < 128) {
        float inv = 1.f / (ssg[tid >> 6] + 1e-16f);
        g_big[(size_t)i * 384 + 128 + tid] = sv[tid] * inv;
        g_big[(size_t)i * 384 + 256 + tid] = se[tid] * inv;
    }
}

// ---------------- block-diagonal weight builders ----------------
__global__ void k_build_w2(const float* __restrict__ ew) {
    int idx = blockIdx.x * blockDim.x + threadIdx.x;
    if (idx >= HD * HD) return;
    int r = idx >> 7, o = idx & 127;
    int h = r >> 6, d = r & 63, h2 = o >> 6, c = o & 63;
    g_w2[idx] = (h == h2) ? ew[(size_t)c * HD + h * 64 + d] : 0.f;
}
__global__ void k_build_w3(const float* __restrict__ ew) {
    int idx = blockIdx.x * blockDim.x + threadIdx.x;
    if (idx >= HD * HD) return;
    int r = idx >> 7, o = idx & 127;
    int h = r >> 6, c = r & 63, h2 = o >> 6, o2 = o & 63;
    g_w3[idx] = (h == h2) ? ew[(size_t)c * HD + h2 * 64 + o2] : 0.f;
}

__global__ void k_biaslin(const float* __restrict__ sb, const float* __restrict__ lw,
                          const float* __restrict__ lb) {
    int o = threadIdx.x;
    if (o >= D64) return;
    float acc = lb[o];
    for (int k2 = 0; k2 < HD; k2++) acc += sb[k2] * lw[(size_t)k2 * D64 + o];
    g_blb[o] = acc;
}

// wcat = [qw | kw | vw | qw@W2]  (128 x 512)
__global__ void k_wcat(const float* __restrict__ qw, const float* __restrict__ kw,
                       const float* __restrict__ vw) {
    int idx = blockIdx.x * blockDim.x + threadIdx.x;
    if (idx >= HD * 512) return;
    int r = idx >> 9, c = idx & 511;
    float v;
    if (c < 128)      v = qw[r * HD + c];
    else if (c < 256) v = kw[r * HD + c - 128];
    else if (c < 384) v = vw[r * HD + c - 256];
    else              v = g_qpw[r * HD + c - 384];
    g_wcat[idx] = v;
}

// bcat = [qb | kb | vb | qb@W2]
__global__ void k_bcat(const float* __restrict__ qb, const float* __restrict__ kb,
                       const float* __restrict__ vb) {
    int c = blockIdx.x * blockDim.x + threadIdx.x;
    if (c >= 512) return;
    float v;
    if (c < 128)      v = qb[c];
    else if (c < 256) v = kb[c - 128];
    else if (c < 384) v = vb[c - 256];
    else {
        int o = c - 384;
        float a = 0.f;
        for (int d = 0; d < HD; d++) a += qb[d] * g_w2[d * HD + o];
        v = a;
    }
    g_bcat[c] = v;
}

// wlin = [sw@lw ; lw ; W3@lw]  (384 x 64), matching big = [cat|t|we]
__global__ void k_wlin(const float* __restrict__ lw) {
    int idx = blockIdx.x * blockDim.x + threadIdx.x;
    if (idx >= 384 * D64) return;
    int r = idx >> 6, c = idx & 63;
    float v;
    if (r < 128)      v = g_swlw[r * D64 + c];
    else if (r < 256) v = lw[(size_t)(r - 128) * D64 + c];
    else              v = g_lw3[(r - 256) * D64 + c];
    g_wlin[idx] = v;
}

// ---------------- fp32 GEMM (weight prep only; rows ~128) ----------------
template <int IN, int OUTT, int ACT, int ACCUM>
__global__ __launch_bounds__(256) void k_gemm2(
        const float* __restrict__ A, const float* __restrict__ W,
        const float* __restrict__ bias, float* __restrict__ C,
        int ldc, int rows, int wld) {
    __shared__ float As[32][132];
    __shared__ float Ws[32][OUTT];
    constexpr int CT = OUTT / 16;
    const int tid = threadIdx.x;
    const int tx = tid & 15;
    const int ty = tid >> 4;
    const int r0 = blockIdx.x * 128;
    const int col0 = blockIdx.y * OUTT;
    float acc[8][CT];
#pragma unroll
    for (int i = 0; i < 8; i++)
#pragma unroll
        for (int j = 0; j < CT; j++) acc[i][j] = 0.f;

    for (int k0 = 0; k0 < IN; k0 += 32) {
#pragma unroll
        for (int t = 0; t < 4; t++) {
            int li = tid + t * 256;
            int r = li >> 3, kq = li & 7;
            int row = r0 + r;
            float4 av = make_float4(0.f, 0.f, 0.f, 0.f);
            if (row < rows) av = *(const float4*)(A + (size_t)row * IN + k0 + kq * 4);
            As[kq * 4 + 0][r] = av.x;
            As[kq * 4 + 1][r] = av.y;
            As[kq * 4 + 2][r] = av.z;
            As[kq * 4 + 3][r] = av.w;
        }
#pragma unroll
        for (int t = 0; t < OUTT / 32; t++) {
            int li = tid + t * 256;
            int kk = li / (OUTT / 4), oq = li % (OUTT / 4);
            ((float4*)(&Ws[kk][0]))[oq] =
                *(const float4*)(W + (size_t)(k0 + kk) * wld + col0 + oq * 4);
        }
        __syncthreads();
#pragma unroll
        for (int kk = 0; kk < 32; kk++) {
            float4 a0 = *(const float4*)&As[kk][ty * 8];
            float4 a1 = *(const float4*)&As[kk][ty * 8 + 4];
            float av[8] = {a0.x, a0.y, a0.z, a0.w, a1.x, a1.y, a1.z, a1.w};
            float wv[CT];
            float4 w0 = *(const float4*)&Ws[kk][tx * CT];
            wv[0] = w0.x; wv[1] = w0.y; wv[2] = w0.z; wv[3] = w0.w;
            if (CT == 8) {
                float4 w1 = *(const float4*)&Ws[kk][tx * CT + 4];
                wv[4] = w1.x; wv[5] = w1.y; wv[6] = w1.z; wv[7] = w1.w;
            }
#pragma unroll
            for (int i = 0; i < 8; i++)
#pragma unroll
                for (int j = 0; j < CT; j++) acc[i][j] += av[i] * wv[j];
        }
        __syncthreads();
    }
#pragma unroll
    for (int i = 0; i < 8; i++) {
        int row = r0 + ty * 8 + i;
        if (row >= rows) continue;
#pragma unroll
        for (int j = 0; j < CT; j++) {
            int col = col0 + tx * CT + j;
            float v = acc[i][j] + (bias ? bias[col] : 0.f);
            if (ACT == 1) v = (v > 0.f) ? v : 0.01f * v;
            float* cp = &C[(size_t)row * ldc + col];
            if (ACCUM) *cp += v; else *cp = v;
        }
    }
}

// ---------------- 3xBF16 tensor-core GEMM with ldmatrix ----------------
__device__ __forceinline__ void mma16(float* c, uint32_t a0, uint32_t a1, uint32_t a2,
                                      uint32_t a3, uint32_t b0, uint32_t b1) {
    asm volatile(
        "mma.sync.aligned.m16n8k16.row.col.f32.bf16.bf16.f32 "
        "{%0,%1,%2,%3}, {%4,%5,%6,%7}, {%8,%9}, {%0,%1,%2,%3};"
        : "+f"(c[0]), "+f"(c[1]), "+f"(c[2]), "+f"(c[3])
        : "r"(a0), "r"(a1), "r"(a2), "r"(a3), "r"(b0), "r"(b1));
}

__device__ __forceinline__ void ldsm_x4(uint32_t& r0, uint32_t& r1, uint32_t& r2,
                                        uint32_t& r3, uint32_t addr) {
    asm volatile("ldmatrix.sync.aligned.m8n8.x4.shared.b16 {%0,%1,%2,%3}, [%4];"
                 : "=r"(r0), "=r"(r1), "=r"(r2), "=r"(r3) : "r"(addr));
}

// C[rows x OUT] = act(A[rows x K](lda) @ W[K x OUT](wld) + bias)
// block: 256 thr = 8 warps (4 m x 2 n), tile 128 x 64, K step 32 (2 mma-k16 steps).
// fp32 -> bf16 hi/lo split once in smem loaders; fragments via ldmatrix.x4.
template <int ACT, int ACCUM>
__global__ __launch_bounds__(256) void k_gemm_bf(
        const float* __restrict__ A, int lda,
        const float* __restrict__ W, int wld,
        const float* __restrict__ bias, float* __restrict__ C,
        int ldc, int rows, int K) {
    __shared__ __align__(16) __nv_bfloat16 Ah[128][40];
    __shared__ __align__(16) __nv_bfloat16 Al[128][40];
    __shared__ __align__(16) __nv_bfloat16 Wh[64][40];
    __shared__ __align__(16) __nv_bfloat16 Wl[64][40];
    const int tid = threadIdx.x, lane = tid & 31, warp = tid >> 5;
    const int warpM = warp & 3, warpN = warp >> 2;
    const int gid = lane >> 2, tig = lane & 3;
    const int r0 = blockIdx.x * 128, col0 = blockIdx.y * 64;
    // ldmatrix lane-address components
    const int a_row_off = lane & 15;           // row within 16-row tile
    const int a_col_off = (lane >> 4) * 8;     // 0 or 8 (k-halves)
    const int b_row_off = ((lane >> 4) & 1) * 8 + (lane & 7);  // n within 16
    const int b_col_off = ((lane >> 3) & 1) * 8;               // k-half
    float acc[2][4][4];
#pragma unroll
    for (int mt = 0; mt < 2; mt++)
#pragma unroll
        for (int nt = 0; nt < 4; nt++)
#pragma unroll
            for (int r = 0; r < 4; r++) acc[mt][nt][r] = 0.f;

    for (int k0 = 0; k0 < K; k0 += 32) {
        // A tile: split to bf16 hi/lo once per element
#pragma unroll
        for (int t = 0; t < 4; t++) {
            int li = tid + t * 256;
            int r = li >> 3, kq = li & 7;
            int row = r0 + r;
            float4 av = make_float4(0.f, 0.f, 0.f, 0.f);
            if (row < rows) av = *(const float4*)(A + (size_t)row * lda + k0 + kq * 4);
            __nv_bfloat16 h0 = __float2bfloat16_rn(av.x);
            __nv_bfloat16 h1 = __float2bfloat16_rn(av.y);
            __nv_bfloat16 h2 = __float2bfloat16_rn(av.z);
            __nv_bfloat16 h3 = __float2bfloat16_rn(av.w);
            Ah[r][kq * 4 + 0] = h0; Ah[r][kq * 4 + 1] = h1;
            Ah[r][kq * 4 + 2] = h2; Ah[r][kq * 4 + 3] = h3;
            Al[r][kq * 4 + 0] = __float2bfloat16_rn(av.x - __bfloat162float(h0));
            Al[r][kq * 4 + 1] = __float2bfloat16_rn(av.y - __bfloat162float(h1));
            Al[r][kq * 4 + 2] = __float2bfloat16_rn(av.z - __bfloat162float(h2));
            Al[r][kq * 4 + 3] = __float2bfloat16_rn(av.w - __bfloat162float(h3));
        }
        // W tile: transposed store Wt[n][k]
#pragma unroll
        for (int t = 0; t < 2; t++) {
            int li = tid + t * 256;
            int kk = li >> 4, oq = li & 15;
            float4 wv = *(const float4*)(W + (size_t)(k0 + kk) * wld + col0 + oq * 4);
            __nv_bfloat16 h0 = __float2bfloat16_rn(wv.x);
            __nv_bfloat16 h1 = __float2bfloat16_rn(wv.y);
            __nv_bfloat16 h2 = __float2bfloat16_rn(wv.z);
            __nv_bfloat16 h3 = __float2bfloat16_rn(wv.w);
            Wh[oq * 4 + 0][kk] = h0; Wh[oq * 4 + 1][kk] = h1;
            Wh[oq * 4 + 2][kk] = h2; Wh[oq * 4 + 3][kk] = h3;
            Wl[oq * 4 + 0][kk] = __float2bfloat16_rn(wv.x - __bfloat162float(h0));
            Wl[oq * 4 + 1][kk] = __float2bfloat16_rn(wv.y - __bfloat162float(h1));
            Wl[oq * 4 + 2][kk] = __float2bfloat16_rn(wv.z - __bfloat162float(h2));
            Wl[oq * 4 + 3][kk] = __float2bfloat16_rn(wv.w - __bfloat162float(h3));
        }
        __syncthreads();
#pragma unroll
        for (int ks = 0; ks < 2; ks++) {
            int kb = ks * 16;
            uint32_t ah[2][4], al[2][4], bh[4][2], bl[4][2];
#pragma unroll
            for (int mt = 0; mt < 2; mt++) {
                int ar = warpM * 32 + mt * 16 + a_row_off;
                int ac = kb + a_col_off;
                ldsm_x4(ah[mt][0], ah[mt][1], ah[mt][2], ah[mt][3],
                        (uint32_t)__cvta_generic_to_shared(&Ah[ar][ac]));
                ldsm_x4(al[mt][0], al[mt][1], al[mt][2], al[mt][3],
                        (uint32_t)__cvta_generic_to_shared(&Al[ar][ac]));
            }
#pragma unroll
            for (int p = 0; p < 2; p++) {
                int br = warpN * 32 + p * 16 + b_row_off;
                int bc = kb + b_col_off;
                ldsm_x4(bh[2 * p][0], bh[2 * p][1], bh[2 * p + 1][0], bh[2 * p + 1][1],
                        (uint32_t)__cvta_generic_to_shared(&Wh[br][bc]));
                ldsm_x4(bl[2 * p][0], bl[2 * p][1], bl[2 * p + 1][0], bl[2 * p + 1][1],
                        (uint32_t)__cvta_generic_to_shared(&Wl[br][bc]));
            }
#pragma unroll
            for (int mt = 0; mt < 2; mt++)
#pragma unroll
                for (int nt = 0; nt < 4; nt++) {
                    mma16(acc[mt][nt], ah[mt][0], ah[mt][1], ah[mt][2], ah[mt][3],
                          bl[nt][0], bl[nt][1]);
                    mma16(acc[mt][nt], al[mt][0], al[mt][1], al[mt][2], al[mt][3],
                          bh[nt][0], bh[nt][1]);
                    mma16(acc[mt][nt], ah[mt][0], ah[mt][1], ah[mt][2], ah[mt][3],
                          bh[nt][0], bh[nt][1]);
                }
        }
        __syncthreads();
    }
    // epilogue
#pragma unroll
    for (int mt = 0; mt < 2; mt++) {
        int rl = r0 + warpM * 32 + mt * 16 + gid;
#pragma unroll
        for (int half = 0; half < 2; half++) {
            int row = rl + half * 8;
            if (row >= rows) continue;
#pragma unroll
            for (int nt = 0; nt < 4; nt++) {
                int col = col0 + warpN * 32 + nt * 8 + tig * 2;
                float v0 = acc[mt][nt][half * 2 + 0];
                float v1 = acc[mt][nt][half * 2 + 1];
                if (bias) { v0 += bias[col]; v1 += bias[col + 1]; }
                if (ACT == 1) {
                    v0 = (v0 > 0.f) ? v0 : 0.01f * v0;
                    v1 = (v1 > 0.f) ? v1 : 0.01f * v1;
                }
                float2* cp = (float2*)(C + (size_t)row * ldc + col);
                if (ACCUM) { float2 o = *cp; v0 += o.x; v1 += o.y; }
                *cp = make_float2(v0, v1);
            }
        }
    }
}

// ---------------- outputs ----------------
__global__ void k_glob_sum(const int* __restrict__ batch) {
    int idx = blockIdx.x * blockDim.x + threadIdx.x;
    if (idx >= NN * D64) return;
    atomicAdd(&g_gsum[batch[idx >> 6] * D64 + (idx & 63)], g_h[idx]);
}

__global__ void k_glob_out(float* __restrict__ out) {
    int idx = blockIdx.x * blockDim.x + threadIdx.x;
    if (idx >= GG * D64) return;
    int g = idx >> 6;
    out[NN * D64 + idx] = g_gsum[idx] / fmaxf(g_cntn[g], 1.f) + g_h[NN * D64 + idx];
}

__global__ void k_ne_out(const int* __restrict__ ne0, const int* __restrict__ ne1,
                         float* __restrict__ out) {
    int idx = blockIdx.x * blockDim.x + threadIdx.x;
    if (idx >= NE_ * D64) return;
    int j = idx >> 6, d = idx & 63;
    out[(NN + GG) * D64 + idx] = g_h[ne0[j] * D64 + d] + g_h[ne1[j] * D64 + d];
}

__global__ void k_cleanup() {
    int idx = blockIdx.x * blockDim.x + threadIdx.x;
    if (idx < GG * D64) g_gsum[idx] = 0.f;
    if (idx < GG) g_cntn[idx] = 0.f;
}

// ---------------- host launcher ----------------
#define GETSYM(ptr, sym) do { void* _p; cudaGetSymbolAddress(&_p, sym); ptr = (decltype(ptr))_p; } while (0)

extern "C" void kernel_launch(void* const* d_in, const int* in_sizes, int n_in,
                              void* d_out, int out_size) {
    const float* x          = (const float*)d_in[0];
    const float* cond       = (const float*)d_in[1];
    const float* edge_attr  = (const float*)d_in[2];
    const int*   edge_index = (const int*)d_in[3];
    const int*   ne_index   = (const int*)d_in[4];
    const int*   batch      = (const int*)d_in[5];
    const float* gen_w  = (const float*)d_in[6];
    const float* gen_b  = (const float*)d_in[7];
    const float* q_w    = (const float*)d_in[8];
    const float* q_b    = (const float*)d_in[9];
    const float* k_w    = (const float*)d_in[10];
    const float* k_b    = (const float*)d_in[11];
    const float* v_w    = (const float*)d_in[12];
    const float* v_b    = (const float*)d_in[13];
    const float* e_w    = (const float*)d_in[14];
    const float* skip_w = (const float*)d_in[15];
    const float* skip_b = (const float*)d_in[16];
    const float* lin_w  = (const float*)d_in[17];
    const float* lin_b  = (const float*)d_in[18];
    const float* ff_w1  = (const float*)d_in[19];
    const float* ff_b1  = (const float*)d_in[20];
    const float* ff_w2  = (const float*)d_in[21];
    const float* ff_b2  = (const float*)d_in[22];
    float* out = (float*)d_out;

    float *h_p, *agg_p, *big_p, *qkvp_p, *lh_p, *ln2_p, *ffh_p;
    float *w2_p, *w3_p, *qpw_p, *swlw_p, *lw3_p, *wcat_p, *bcat_p, *wlin_p, *blb_p;
    GETSYM(h_p, g_h);       GETSYM(agg_p, g_agg);
    GETSYM(big_p, g_big);   GETSYM(qkvp_p, g_qkvp); GETSYM(lh_p, g_lh);
    GETSYM(ln2_p, g_ln2);   GETSYM(ffh_p, g_ffh);
    GETSYM(w2_p, g_w2);     GETSYM(w3_p, g_w3);     GETSYM(qpw_p, g_qpw);
    GETSYM(swlw_p, g_swlw); GETSYM(lw3_p, g_lw3);   GETSYM(wcat_p, g_wcat);
    GETSYM(bcat_p, g_bcat); GETSYM(wlin_p, g_wlin); GETSYM(blb_p, g_blb);

    const int T = 256;
    const int GRID_N = CDIV(NAUG, 128);
    cudaStream_t st = 0;

    // ---- setup ----
    k_build_edges<<<CDIV(MM, T), T, 0, st>>>(edge_index, edge_index + EE, batch);
    k_scanA<<<NB_SCAN, 256, 0, st>>>();
    k_scanB<<<1, 256, 0, st>>>();
    k_scanC<<<NB_SCAN, 256, 0, st>>>();
    k_scatter<<<CDIV(MM, T), T, 0, st>>>();
    k_abatch<<<CDIV(NAUG, T), T, 0, st>>>(batch);
    k_cntn<<<CDIV(NN, T), T, 0, st>>>(batch);
    k_init_h<<<CDIV(NAUG * D64, T), T, 0, st>>>(x, cond);
    k_tail_ep<<<CDIV(2 * NN * D64, T), T, 0, st>>>();
    k_tail_csr<<<CDIV(NAUG * 32, T), T, 0, st>>>(edge_attr);
    k_eperm<<<CDIV(MM * 32, T), T, 0, st>>>(edge_attr);

    // ---- layers ----
    for (int i = 0; i < LL; i++) {
        const float* gw  = gen_w  + (size_t)i * D64 * D64;
        const float* gb  = gen_b  + (size_t)i * D64;
        const float* qw  = q_w    + (size_t)i * HD * HD;
        const float* qb  = q_b    + (size_t)i * HD;
        const float* kw  = k_w    + (size_t)i * HD * HD;
        const float* kb  = k_b    + (size_t)i * HD;
        const float* vw  = v_w    + (size_t)i * HD * HD;
        const float* vb  = v_b    + (size_t)i * HD;
        const float* ew  = e_w    + (size_t)i * D64 * HD;
        const float* sw  = skip_w + (size_t)i * HD * HD;
        const float* sb  = skip_b + (size_t)i * HD;
        const float* lw  = lin_w  + (size_t)i * HD * D64;
        const float* lb  = lin_b  + (size_t)i * D64;
        const float* f1w = ff_w1  + (size_t)i * D64 * 4 * D64;
        const float* f1b = ff_b1  + (size_t)i * 4 * D64;
        const float* f2w = ff_w2  + (size_t)i * 4 * D64 * D64;
        const float* f2b = ff_b2  + (size_t)i * D64;

        // weight precomputes (fp32, tiny)
        k_build_w2<<<CDIV(HD * HD, T), T, 0, st>>>(ew);
        k_build_w3<<<CDIV(HD * HD, T), T, 0, st>>>(ew);
        k_gemm2<HD, HD, 0, 0><<<dim3(1, 1), T, 0, st>>>(qw, w2_p, nullptr, qpw_p, HD, HD, HD);
        k_gemm2<HD, D64, 0, 0><<<dim3(1, 1), T, 0, st>>>(sw, lw, nullptr, swlw_p, D64, HD, D64);
        k_gemm2<HD, D64, 0, 0><<<dim3(1, 1), T, 0, st>>>(w3_p, lw, nullptr, lw3_p, D64, HD, D64);
        k_biaslin<<<1, 64, 0, st>>>(sb, lw, lb);
        k_wcat<<<CDIV(HD * 512, T), T, 0, st>>>(qw, kw, vw);
        k_bcat<<<2, 256, 0, st>>>(qb, kb, vb);
        k_wlin<<<CDIV(384 * D64, T), T, 0, st>>>(lw);

        // LN1 -> hn + big[:, :64]
        k_ln_stats<<<CDIV(NAUG * 32, T), T, 0, st>>>(h_p);
        k_ln_final<<<1, GG, 0, st>>>();
        k_ln_apply2<<<CDIV(NAUG * D64, T), T, 0, st>>>(h_p);

        // gen_conv -> agg ; gemm -> big[:, 64:128]
        k_gen<<<CDIV(NN * 32, T), T, 0, st>>>();
        k_gen_v<<<GG, T, 0, st>>>();
        k_gemm_bf<0, 0><<<dim3(GRID_N, 1), T, 0, st>>>(agg_p, D64, gw, D64, gb,
                                                       big_p + 64, 384, NAUG, D64);

        // fused q|k|v|qp projection
        k_gemm_bf<0, 0><<<dim3(GRID_N, 8), T, 0, st>>>(big_p, 384, wcat_p, 512, bcat_p,
                                                       qkvp_p, 512, NAUG, HD);

        // fused single-pass attention -> big[:, 128:256] (t), big[:, 256:384] (we)
        k_attn<<<CDIV(NN * 32, T), T, 0, st>>>();
        k_attn_v<<<GG, T, 0, st>>>();

        // lh = big @ wlin + blb
        k_gemm_bf<0, 0><<<dim3(GRID_N, 1), T, 0, st>>>(big_p, 384, wlin_p, D64, blb_p,
                                                       lh_p, D64, NAUG, 384);

        // LN2
        k_ln_stats<<<CDIV(NAUG * 32, T), T, 0, st>>>(lh_p);
        k_ln_final<<<1, GG, 0, st>>>();
        k_ln_apply<<<CDIV(NAUG * D64, T), T, 0, st>>>(lh_p, ln2_p);

        // FF + residual
        k_gemm_bf<1, 0><<<dim3(GRID_N, 4), T, 0, st>>>(ln2_p, D64, f1w, 256, f1b,
                                                       ffh_p, 256, NAUG, D64);
        k_gemm_bf<0, 1><<<dim3(GRID_N, 1), T, 0, st>>>(ffh_p, 256, f2w, D64, f2b,
                                                       h_p, D64, NAUG, 256);
    }

    // ---- outputs ----
    cudaMemcpyAsync(out, h_p, sizeof(float) * NN * D64, cudaMemcpyDeviceToDevice, st);
    k_glob_sum<<<CDIV(NN * D64, T), T, 0, st>>>(batch);
    k_glob_out<<<CDIV(GG * D64, T), T, 0, st>>>(out);
    k_ne_out<<<CDIV(NE_ * D64, T), T, 0, st>>>(ne_index, ne_index + NE_, out);
    k_cleanup<<<CDIV(GG * D64, T), T, 0, st>>>();
}

// round 8
// speedup vs baseline: 1.0215x; 1.0215x over previous
#include <cuda_runtime.h>
#include <cuda_bf16.h>
#include <math.h>
#include <stdint.h>

// Problem constants
#define D64   64
#define HH    2
#define HD    128
#define LL    3
#define NN    50000
#define GG    128
#define EE    600000
#define NE_   300000
#define NAUG  (NN + GG)          // 50128
#define M0    (EE + 2 * NN)      // 700000
#define MM    (M0 + NAUG)        // 750128
#define TAILR (MM - EE)          // 150128
#define NB_SCAN ((NAUG + 255) / 256)   // 196

#define CDIV(a, b) (((a) + (b) - 1) / (b))

// ---------------- device scratch (static, no allocs) ----------------
__device__ int    g_src[MM];
__device__ int    g_dst[MM];
__device__ int    g_deg[NAUG];
__device__ int    g_rowptr[NAUG + 1];
__device__ int    g_bsum[256];
__device__ int    g_fill[NAUG];
__device__ int    g_esrc[MM];
__device__ int    g_eid[MM];
__device__ float  g_eperm[(size_t)MM * D64];     // e_aug rows in CSR order
__device__ float  g_tail[(size_t)TAILR * D64];   // e_aug rows >= EE
__device__ float  g_h[NAUG * D64];
__device__ float  g_hn[NAUG * D64];
__device__ float  g_big[(size_t)NAUG * 384];     // [hn(64)|geno(64) | t(128) | we(128)]
__device__ float  g_qkvp[(size_t)NAUG * 512];    // [q | k | v | qp]
__device__ float  g_lh[NAUG * D64];
__device__ float  g_ln2[NAUG * D64];
__device__ float  g_ffh[(size_t)NAUG * 256];
__device__ float  g_w2[HD * HD];
__device__ float  g_w3[HD * HD];
__device__ float  g_qpw[HD * HD];
__device__ float  g_swlw[HD * D64];
__device__ float  g_lw3[HD * D64];
__device__ float  g_wcat[HD * 512];
__device__ float  g_bcat[512];
__device__ float  g_wlin[384 * D64];
__device__ float  g_blb[D64];
__device__ float  g_wcat2[HD * 512];             // [wcat_top; gw@wcat_bot]
__device__ float  g_bcat2[512];
__device__ float  g_wlin2[384 * D64];            // [swlw_top; gw@swlw_bot; lw; lw3]
__device__ float  g_blb2[D64];
__device__ float  g_cntn[GG];
__device__ double g_lsum[GG];
__device__ double g_lsumsq[GG];
__device__ float  g_mean[GG];
__device__ float  g_rstd[GG];
__device__ int    g_abatch[NAUG];
__device__ float  g_gsum[GG * D64];

// ---------------- setup kernels ----------------
__global__ void k_build_edges(const int* __restrict__ ei0, const int* __restrict__ ei1,
                              const int* __restrict__ batch) {
    int m = blockIdx.x * blockDim.x + threadIdx.x;
    if (m >= MM) return;
    int s, d;
    if (m < EE)               { s = ei0[m]; d = ei1[m]; }
    else if (m < EE + NN)     { int i = m - EE;          s = i;             d = batch[i] + NN; }
    else if (m < EE + 2 * NN) { int i = m - EE - NN;     s = batch[i] + NN; d = i; }
    else                      { int i = m - EE - 2 * NN; s = i;             d = i; }
    g_src[m] = s; g_dst[m] = d;
    atomicAdd(&g_deg[d], 1);
}

__global__ void k_scanA() {
    __shared__ int sh[256];
    int t = threadIdx.x;
    int i = blockIdx.x * 256 + t;
    int v = (i < NAUG) ? g_deg[i] : 0;
    sh[t] = v;
    __syncthreads();
    for (int off = 1; off < 256; off <<= 1) {
        int a = (t >= off) ? sh[t - off] : 0;
        __syncthreads();
        sh[t] += a;
        __syncthreads();
    }
    if (i < NAUG) g_rowptr[i] = sh[t] - v;
    if (t == 255) g_bsum[blockIdx.x] = sh[255];
}

__global__ void k_scanB() {
    __shared__ int sh[256];
    int t = threadIdx.x;
    int v = (t < NB_SCAN) ? g_bsum[t] : 0;
    sh[t] = v;
    __syncthreads();
    for (int off = 1; off < 256; off <<= 1) {
        int a = (t >= off) ? sh[t - off] : 0;
        __syncthreads();
        sh[t] += a;
        __syncthreads();
    }
    if (t < NB_SCAN) g_bsum[t] = sh[t] - v;
}

__global__ void k_scanC() {
    int i = blockIdx.x * 256 + threadIdx.x;
    if (i < NAUG) {
        int r = g_rowptr[i] + g_bsum[i >> 8];
        g_rowptr[i] = r;
        g_fill[i] = r;
        g_deg[i] = 0;                 // self-clean
    }
    if (i == 0) g_rowptr[NAUG] = MM;
}

__global__ void k_scatter() {
    int m = blockIdx.x * blockDim.x + threadIdx.x;
    if (m >= MM) return;
    int pos = atomicAdd(&g_fill[g_dst[m]], 1);
    g_esrc[pos] = g_src[m];
    g_eid[pos]  = m;
}

__global__ void k_abatch(const int* __restrict__ batch) {
    int i = blockIdx.x * blockDim.x + threadIdx.x;
    if (i >= NAUG) return;
    g_abatch[i] = (i < NN) ? batch[i] : (i - NN);
}

__global__ void k_cntn(const int* __restrict__ batch) {
    int i = blockIdx.x * blockDim.x + threadIdx.x;
    if (i >= NN) return;
    atomicAdd(&g_cntn[batch[i]], 1.f);
}

__global__ void k_init_h(const float* __restrict__ x, const float* __restrict__ cond) {
    int idx = blockIdx.x * blockDim.x + threadIdx.x;
    if (idx >= NAUG * D64) return;
    g_h[idx] = (idx < NN * D64) ? x[idx] : cond[idx - NN * D64];
}

__global__ void k_tail_ep() {
    int idx = blockIdx.x * blockDim.x + threadIdx.x;
    if (idx >= 2 * NN * D64) return;
    g_tail[idx] = ((idx & 63) == 0) ? 1.f : 0.f;
}

__global__ void k_tail_csr(const float* __restrict__ edge_attr) {
    int i = (blockIdx.x * blockDim.x + threadIdx.x) >> 5;
    int lane = threadIdx.x & 31;
    if (i >= NAUG) return;
    float2 acc = {0.f, 0.f};
    float cnt = 0.f;
    int e0 = g_rowptr[i], e1 = g_rowptr[i + 1];
    for (int e = e0; e < e1; e++) {
        int m = g_eid[e];
        if (m < EE) {
            float2 ev = ((const float2*)(edge_attr + (size_t)m * D64))[lane];
            acc.x += ev.x; acc.y += ev.y;
            cnt += 1.f;
        } else if (m < M0) {
            if (lane == 0) acc.x += 1.f;
            cnt += 1.f;
        }
    }
    float invc = 1.f / fmaxf(cnt, 1.f);
    float2 o = {acc.x * invc, acc.y * invc};
    ((float2*)(g_tail + (size_t)(2 * NN + i) * D64))[lane] = o;
}

// permute e_aug rows into CSR order
__global__ void k_eperm(const float* __restrict__ edge_attr) {
    int gw = (blockIdx.x * blockDim.x + threadIdx.x) >> 5;
    int lane = threadIdx.x & 31;
    if (gw >= MM) return;
    int m = g_eid[gw];
    const float* ep = (m < EE) ? edge_attr + (size_t)m * D64
                               : g_tail + (size_t)(m - EE) * D64;
    float2 v = ((const float2*)ep)[lane];
    ((float2*)(g_eperm + (size_t)gw * D64))[lane] = v;
}

// ---------------- graph layernorm ----------------
__global__ void k_ln_stats(const float* __restrict__ X) {
    int i = (blockIdx.x * blockDim.x + threadIdx.x) >> 5;
    int lane = threadIdx.x & 31;
    if (i >= NAUG) return;
    float2 v = ((const float2*)(X + (size_t)i * D64))[lane];
    float s  = v.x + v.y;
    float ss = v.x * v.x + v.y * v.y;
#pragma unroll
    for (int off = 16; off; off >>= 1) {
        s  += __shfl_xor_sync(0xffffffffu, s, off);
        ss += __shfl_xor_sync(0xffffffffu, ss, off);
    }
    if (lane == 0) {
        int b = g_abatch[i];
        atomicAdd(&g_lsum[b], (double)s);
        atomicAdd(&g_lsumsq[b], (double)ss);
    }
}

__global__ void k_ln_final() {
    int g = threadIdx.x;
    if (g >= GG) return;
    double norm = (double)fmaxf(g_cntn[g] + 1.f, 1.f) * D64;
    double mean = g_lsum[g] / norm;
    double var  = g_lsumsq[g] / norm - mean * mean;
    g_mean[g] = (float)mean;
    g_rstd[g] = rsqrtf((float)var + 1e-5f);
    g_lsum[g] = 0.0;            // self-clean
    g_lsumsq[g] = 0.0;
}

// writes hn AND big[:, 0:64]
__global__ void k_ln_apply2(const float* __restrict__ X) {
    int idx = blockIdx.x * blockDim.x + threadIdx.x;
    if (idx >= NAUG * D64) return;
    int i = idx >> 6, d = idx & 63;
    int b = g_abatch[i];
    float v = (X[idx] - g_mean[b]) * g_rstd[b];
    g_hn[idx] = v;
    g_big[(size_t)i * 384 + d] = v;
}

__global__ void k_ln_apply(const float* __restrict__ X, float* __restrict__ Y) {
    int idx = blockIdx.x * blockDim.x + threadIdx.x;
    if (idx >= NAUG * D64) return;
    int b = g_abatch[idx >> 6];
    Y[idx] = (X[idx] - g_mean[b]) * g_rstd[b];
}

// ---------------- gen_conv: writes pre-GEMM output straight into big[:,64:128] ----------------
__global__ void k_gen() {
    int i = (blockIdx.x * blockDim.x + threadIdx.x) >> 5;
    int lane = threadIdx.x & 31;
    if (i >= NN) return;
    float2 acc = {0.f, 0.f};
    int e0 = g_rowptr[i], e1 = g_rowptr[i + 1];
    for (int e = e0; e < e1; e++) {
        int s = g_esrc[e];
        float2 ev = ((const float2*)(g_eperm + (size_t)e * D64))[lane];
        float2 hv = ((const float2*)(g_hn + (size_t)s * D64))[lane];
        acc.x += fmaxf(hv.x + ev.x, 0.f) + 1e-7f;
        acc.y += fmaxf(hv.y + ev.y, 0.f) + 1e-7f;
    }
    float2 hi = ((const float2*)(g_hn + (size_t)i * D64))[lane];
    float2 o = {acc.x + hi.x, acc.y + hi.y};
    ((float2*)(g_big + (size_t)i * 384 + 64))[lane] = o;
}

__global__ void k_gen_v() {
    __shared__ float sa[64];
    int i = NN + blockIdx.x;
    int tid = threadIdx.x, lane = tid & 31, wid = tid >> 5;
    if (tid < 64) sa[tid] = 0.f;
    __syncthreads();
    int e0 = g_rowptr[i], e1 = g_rowptr[i + 1];
    float2 acc = {0.f, 0.f};
    for (int e = e0 + wid; e < e1; e += 8) {
        int s = g_esrc[e];
        float2 ev = ((const float2*)(g_eperm + (size_t)e * D64))[lane];
        float2 hv = ((const float2*)(g_hn + (size_t)s * D64))[lane];
        acc.x += fmaxf(hv.x + ev.x, 0.f) + 1e-7f;
        acc.y += fmaxf(hv.y + ev.y, 0.f) + 1e-7f;
    }
    atomicAdd(&sa[2 * lane],     acc.x);
    atomicAdd(&sa[2 * lane + 1], acc.y);
    __syncthreads();
    if (tid < 64) g_big[(size_t)i * 384 + 64 + tid] = sa[tid] + g_hn[(size_t)i * D64 + tid];
}

// ---------------- fused single-pass attention (online softmax) ----------------
__global__ void k_attn() {
    int i = (blockIdx.x * blockDim.x + threadIdx.x) >> 5;
    int lane = threadIdx.x & 31;
    if (i >= NN) return;
    int el = lane & 15;
    float4 q4  = *(const float4*)(g_qkvp + (size_t)i * 512 + 4 * lane);
    float4 qp4 = *(const float4*)(g_qkvp + (size_t)i * 512 + 384 + 4 * lane);
    int e0 = g_rowptr[i], e1 = g_rowptr[i + 1];
    float mx = -INFINITY, sum = 0.f;
    float4 vacc = {0.f, 0.f, 0.f, 0.f};
    float4 eacc = {0.f, 0.f, 0.f, 0.f};
    for (int e = e0; e < e1; e++) {
        int s = g_esrc[e];
        const float* ep = g_eperm + (size_t)e * D64;
        float4 k4 = *(const float4*)(g_qkvp + (size_t)s * 512 + 128 + 4 * lane);
        float4 e4 = *(const float4*)(ep + 4 * el);
        float p = q4.x * k4.x + q4.y * k4.y + q4.z * k4.z + q4.w * k4.w
                + qp4.x * e4.x + qp4.y * e4.y + qp4.z * e4.z + qp4.w * e4.w;
        p += __shfl_xor_sync(0xffffffffu, p, 1);
        p += __shfl_xor_sync(0xffffffffu, p, 2);
        p += __shfl_xor_sync(0xffffffffu, p, 4);
        p += __shfl_xor_sync(0xffffffffu, p, 8);
        float a = p * 0.125f;
        if (a > mx) {
            float sc = expf(mx - a);
            sum *= sc;
            vacc.x *= sc; vacc.y *= sc; vacc.z *= sc; vacc.w *= sc;
            eacc.x *= sc; eacc.y *= sc; eacc.z *= sc; eacc.w *= sc;
            mx = a;
        }
        float w = expf(a - mx);
        sum += w;
        float4 v4 = *(const float4*)(g_qkvp + (size_t)s * 512 + 256 + 4 * lane);
        vacc.x += w * v4.x; vacc.y += w * v4.y; vacc.z += w * v4.z; vacc.w += w * v4.w;
        eacc.x += w * e4.x; eacc.y += w * e4.y; eacc.z += w * e4.z; eacc.w += w * e4.w;
    }
    float inv = 1.f / (sum + 1e-16f);
    float4 to = {vacc.x * inv, vacc.y * inv, vacc.z * inv, vacc.w * inv};
    float4 wo = {eacc.x * inv, eacc.y * inv, eacc.z * inv, eacc.w * inv};
    *(float4*)(g_big + (size_t)i * 384 + 128 + 4 * lane) = to;
    *(float4*)(g_big + (size_t)i * 384 + 256 + 4 * lane) = wo;
}

__global__ void k_attn_v() {
    __shared__ float sv[128];
    __shared__ float se[128];
    __shared__ float ssg[2];
    __shared__ float swmx[16];
    __shared__ float gmx[2];
    int i = NN + blockIdx.x;
    int tid = threadIdx.x, lane = tid & 31, wid = tid >> 5;
    int el = lane & 15;
    int hh = lane >> 4;
    if (tid < 128) { sv[tid] = 0.f; se[tid] = 0.f; }
    if (tid < 2) ssg[tid] = 0.f;
    __syncthreads();
    float4 q4  = *(const float4*)(g_qkvp + (size_t)i * 512 + 4 * lane);
    float4 qp4 = *(const float4*)(g_qkvp + (size_t)i * 512 + 384 + 4 * lane);
    int e0 = g_rowptr[i], e1 = g_rowptr[i + 1];
    float mx = -INFINITY, sum = 0.f;
    float4 vacc = {0.f, 0.f, 0.f, 0.f};
    float4 eacc = {0.f, 0.f, 0.f, 0.f};
    for (int e = e0 + wid; e < e1; e += 8) {
        int s = g_esrc[e];
        const float* ep = g_eperm + (size_t)e * D64;
        float4 k4 = *(const float4*)(g_qkvp + (size_t)s * 512 + 128 + 4 * lane);
        float4 e4 = *(const float4*)(ep + 4 * el);
        float p = q4.x * k4.x + q4.y * k4.y + q4.z * k4.z + q4.w * k4.w
                + qp4.x * e4.x + qp4.y * e4.y + qp4.z * e4.z + qp4.w * e4.w;
        p += __shfl_xor_sync(0xffffffffu, p, 1);
        p += __shfl_xor_sync(0xffffffffu, p, 2);
        p += __shfl_xor_sync(0xffffffffu, p, 4);
        p += __shfl_xor_sync(0xffffffffu, p, 8);
        float a = p * 0.125f;
        if (a > mx) {
            float sc = expf(mx - a);
            sum *= sc;
            vacc.x *= sc; vacc.y *= sc; vacc.z *= sc; vacc.w *= sc;
            eacc.x *= sc; eacc.y *= sc; eacc.z *= sc; eacc.w *= sc;
            mx = a;
        }
        float w = expf(a - mx);
        sum += w;
        float4 v4 = *(const float4*)(g_qkvp + (size_t)s * 512 + 256 + 4 * lane);
        vacc.x += w * v4.x; vacc.y += w * v4.y; vacc.z += w * v4.z; vacc.w += w * v4.w;
        eacc.x += w * e4.x; eacc.y += w * e4.y; eacc.z += w * e4.z; eacc.w += w * e4.w;
    }
    if (el == 0) swmx[wid * 2 + hh] = mx;
    __syncthreads();
    if (tid < 2) {
        float m = -INFINITY;
#pragma unroll
        for (int w = 0; w < 8; w++) m = fmaxf(m, swmx[w * 2 + tid]);
        gmx[tid] = m;
    }
    __syncthreads();
    float sc = expf(mx - gmx[hh]);
    atomicAdd(&sv[4 * lane],     vacc.x * sc); atomicAdd(&sv[4 * lane + 1], vacc.y * sc);
    atomicAdd(&sv[4 * lane + 2], vacc.z * sc); atomicAdd(&sv[4 * lane + 3], vacc.w * sc);
    atomicAdd(&se[4 * lane],     eacc.x * sc); atomicAdd(&se[4 * lane + 1], eacc.y * sc);
    atomicAdd(&se[4 * lane + 2], eacc.z * sc); atomicAdd(&se[4 * lane + 3], eacc.w * sc);
    if (el == 0) atomicAdd(&ssg[hh], sum * sc);
    __syncthreads();
    if (tid < 128) {
        float inv = 1.f / (ssg[tid >> 6] + 1e-16f);
        g_big[(size_t)i * 384 + 128 + tid] = sv[tid] * inv;
        g_big[(size_t)i * 384 + 256 + tid] = se[tid] * inv;
    }
}

// ---------------- weight builders ----------------
__global__ void k_build_w2(const float* __restrict__ ew) {
    int idx = blockIdx.x * blockDim.x + threadIdx.x;
    if (idx >= HD * HD) return;
    int r = idx >> 7, o = idx & 127;
    int h = r >> 6, d = r & 63, h2 = o >> 6, c = o & 63;
    g_w2[idx] = (h == h2) ? ew[(size_t)c * HD + h * 64 + d] : 0.f;
}
__global__ void k_build_w3(const float* __restrict__ ew) {
    int idx = blockIdx.x * blockDim.x + threadIdx.x;
    if (idx >= HD * HD) return;
    int r = idx >> 7, o = idx & 127;
    int h = r >> 6, c = r & 63, h2 = o >> 6, o2 = o & 63;
    g_w3[idx] = (h == h2) ? ew[(size_t)c * HD + h2 * 64 + o2] : 0.f;
}

__global__ void k_biaslin(const float* __restrict__ sb, const float* __restrict__ lw,
                          const float* __restrict__ lb) {
    int o = threadIdx.x;
    if (o >= D64) return;
    float acc = lb[o];
    for (int k2 = 0; k2 < HD; k2++) acc += sb[k2] * lw[(size_t)k2 * D64 + o];
    g_blb[o] = acc;
}

// wcat = [qw | kw | vw | qw@W2]  (128 x 512)
__global__ void k_wcat(const float* __restrict__ qw, const float* __restrict__ kw,
                       const float* __restrict__ vw) {
    int idx = blockIdx.x * blockDim.x + threadIdx.x;
    if (idx >= HD * 512) return;
    int r = idx >> 9, c = idx & 511;
    float v;
    if (c < 128)      v = qw[r * HD + c];
    else if (c < 256) v = kw[r * HD + c - 128];
    else if (c < 384) v = vw[r * HD + c - 256];
    else              v = g_qpw[r * HD + c - 384];
    g_wcat[idx] = v;
}

// bcat = [qb | kb | vb | qb@W2]
__global__ void k_bcat(const float* __restrict__ qb, const float* __restrict__ kb,
                       const float* __restrict__ vb) {
    int c = blockIdx.x * blockDim.x + threadIdx.x;
    if (c >= 512) return;
    float v;
    if (c < 128)      v = qb[c];
    else if (c < 256) v = kb[c - 128];
    else if (c < 384) v = vb[c - 256];
    else {
        int o = c - 384;
        float a = 0.f;
        for (int d = 0; d < HD; d++) a += qb[d] * g_w2[d * HD + o];
        v = a;
    }
    g_bcat[c] = v;
}

// wlin = [sw@lw ; lw ; W3@lw]  (384 x 64)
__global__ void k_wlin(const float* __restrict__ lw) {
    int idx = blockIdx.x * blockDim.x + threadIdx.x;
    if (idx >= 384 * D64) return;
    int r = idx >> 6, c = idx & 63;
    float v;
    if (r < 128)      v = g_swlw[r * D64 + c];
    else if (r < 256) v = lw[(size_t)(r - 128) * D64 + c];
    else              v = g_lw3[(r - 256) * D64 + c];
    g_wlin[idx] = v;
}

// fold gen GEMM into weights:
// wcat2 rows 0-63 = wcat rows 0-63 (copied here); rows 64-127 = gw @ wcat[64:128] (gemm)
// wlin2 rows 0-63, 128-383 copied; rows 64-127 = gw @ wlin[64:128] (gemm)
__global__ void k_fold_copy() {
    int idx = blockIdx.x * blockDim.x + threadIdx.x;
    // wcat2 top: 64*512
    if (idx < 64 * 512) g_wcat2[idx] = g_wcat[idx];
    // wlin2 rows 0-63: 64*64
    int j = idx - 64 * 512;
    if (j >= 0 && j < 64 * 64) g_wlin2[j] = g_wlin[j];
    // wlin2 rows 128-383: 256*64
    int k2 = j - 64 * 64;
    if (k2 >= 0 && k2 < 256 * 64) g_wlin2[128 * 64 + k2] = g_wlin[128 * 64 + k2];
}

// bcat2 = bcat + gb @ wcat[64:128] ; blb2 = blb + gb @ wlin[64:128]
__global__ void k_fold_bias(const float* __restrict__ gb) {
    int c = blockIdx.x * blockDim.x + threadIdx.x;
    if (c < 512) {
        float a = g_bcat[c];
        for (int d = 0; d < 64; d++) a += gb[d] * g_wcat[(64 + d) * 512 + c];
        g_bcat2[c] = a;
    } else if (c < 512 + 64) {
        int o = c - 512;
        float a = g_blb[o];
        for (int d = 0; d < 64; d++) a += gb[d] * g_wlin[(64 + d) * 64 + o];
        g_blb2[o] = a;
    }
}

// ---------------- fp32 GEMM (weight prep only; rows <= 128) ----------------
template <int IN, int OUTT, int ACT, int ACCUM>
__global__ __launch_bounds__(256) void k_gemm2(
        const float* __restrict__ A, const float* __restrict__ W,
        const float* __restrict__ bias, float* __restrict__ C,
        int ldc, int rows, int wld) {
    __shared__ float As[32][132];
    __shared__ float Ws[32][OUTT];
    constexpr int CT = OUTT / 16;
    const int tid = threadIdx.x;
    const int tx = tid & 15;
    const int ty = tid >> 4;
    const int r0 = blockIdx.x * 128;
    const int col0 = blockIdx.y * OUTT;
    float acc[8][CT];
#pragma unroll
    for (int i = 0; i < 8; i++)
#pragma unroll
        for (int j = 0; j < CT; j++) acc[i][j] = 0.f;

    for (int k0 = 0; k0 < IN; k0 += 32) {
#pragma unroll
        for (int t = 0; t < 4; t++) {
            int li = tid + t * 256;
            int r = li >> 3, kq = li & 7;
            int row = r0 + r;
            float4 av = make_float4(0.f, 0.f, 0.f, 0.f);
            if (row < rows) av = *(const float4*)(A + (size_t)row * IN + k0 + kq * 4);
            As[kq * 4 + 0][r] = av.x;
            As[kq * 4 + 1][r] = av.y;
            As[kq * 4 + 2][r] = av.z;
            As[kq * 4 + 3][r] = av.w;
        }
#pragma unroll
        for (int t = 0; t < OUTT / 32; t++) {
            int li = tid + t * 256;
            int kk = li / (OUTT / 4), oq = li % (OUTT / 4);
            ((float4*)(&Ws[kk][0]))[oq] =
                *(const float4*)(W + (size_t)(k0 + kk) * wld + col0 + oq * 4);
        }
        __syncthreads();
#pragma unroll
        for (int kk = 0; kk < 32; kk++) {
            float4 a0 = *(const float4*)&As[kk][ty * 8];
            float4 a1 = *(const float4*)&As[kk][ty * 8 + 4];
            float av[8] = {a0.x, a0.y, a0.z, a0.w, a1.x, a1.y, a1.z, a1.w};
            float wv[CT];
            float4 w0 = *(const float4*)&Ws[kk][tx * CT];
            wv[0] = w0.x; wv[1] = w0.y; wv[2] = w0.z; wv[3] = w0.w;
            if (CT == 8) {
                float4 w1 = *(const float4*)&Ws[kk][tx * CT + 4];
                wv[4] = w1.x; wv[5] = w1.y; wv[6] = w1.z; wv[7] = w1.w;
            }
#pragma unroll
            for (int i = 0; i < 8; i++)
#pragma unroll
                for (int j = 0; j < CT; j++) acc[i][j] += av[i] * wv[j];
        }
        __syncthreads();
    }
#pragma unroll
    for (int i = 0; i < 8; i++) {
        int row = r0 + ty * 8 + i;
        if (row >= rows) continue;
#pragma unroll
        for (int j = 0; j < CT; j++) {
            int col = col0 + tx * CT + j;
            float v = acc[i][j] + (bias ? bias[col] : 0.f);
            if (ACT == 1) v = (v > 0.f) ? v : 0.01f * v;
            float* cp = &C[(size_t)row * ldc + col];
            if (ACCUM) *cp += v; else *cp = v;
        }
    }
}

// ---------------- 3xBF16 tensor-core GEMM (R6 scalar-LDS version) ----------------
__device__ __forceinline__ void mma16(float* c, uint32_t a0, uint32_t a1, uint32_t a2,
                                      uint32_t a3, uint32_t b0, uint32_t b1) {
    asm volatile(
        "mma.sync.aligned.m16n8k16.row.col.f32.bf16.bf16.f32 "
        "{%0,%1,%2,%3}, {%4,%5,%6,%7}, {%8,%9}, {%0,%1,%2,%3};"
        : "+f"(c[0]), "+f"(c[1]), "+f"(c[2]), "+f"(c[3])
        : "r"(a0), "r"(a1), "r"(a2), "r"(a3), "r"(b0), "r"(b1));
}

template <int ACT, int ACCUM>
__global__ __launch_bounds__(256) void k_gemm_bf(
        const float* __restrict__ A, int lda,
        const float* __restrict__ W, int wld,
        const float* __restrict__ bias, float* __restrict__ C,
        int ldc, int rows, int K) {
    __shared__ __align__(16) __nv_bfloat16 Ah[128][40];
    __shared__ __align__(16) __nv_bfloat16 Al[128][40];
    __shared__ __align__(16) __nv_bfloat16 Wh[64][40];
    __shared__ __align__(16) __nv_bfloat16 Wl[64][40];
    const int tid = threadIdx.x, lane = tid & 31, warp = tid >> 5;
    const int warpM = warp & 3, warpN = warp >> 2;
    const int gid = lane >> 2, tig = lane & 3;
    const int r0 = blockIdx.x * 128, col0 = blockIdx.y * 64;
    float acc[2][4][4];
#pragma unroll
    for (int mt = 0; mt < 2; mt++)
#pragma unroll
        for (int nt = 0; nt < 4; nt++)
#pragma unroll
            for (int r = 0; r < 4; r++) acc[mt][nt][r] = 0.f;

    for (int k0 = 0; k0 < K; k0 += 32) {
#pragma unroll
        for (int t = 0; t < 4; t++) {
            int li = tid + t * 256;
            int r = li >> 3, kq = li & 7;
            int row = r0 + r;
            float4 av = make_float4(0.f, 0.f, 0.f, 0.f);
            if (row < rows) av = *(const float4*)(A + (size_t)row * lda + k0 + kq * 4);
            __nv_bfloat16 h0 = __float2bfloat16_rn(av.x);
            __nv_bfloat16 h1 = __float2bfloat16_rn(av.y);
            __nv_bfloat16 h2 = __float2bfloat16_rn(av.z);
            __nv_bfloat16 h3 = __float2bfloat16_rn(av.w);
            Ah[r][kq * 4 + 0] = h0; Ah[r][kq * 4 + 1] = h1;
            Ah[r][kq * 4 + 2] = h2; Ah[r][kq * 4 + 3] = h3;
            Al[r][kq * 4 + 0] = __float2bfloat16_rn(av.x - __bfloat162float(h0));
            Al[r][kq * 4 + 1] = __float2bfloat16_rn(av.y - __bfloat162float(h1));
            Al[r][kq * 4 + 2] = __float2bfloat16_rn(av.z - __bfloat162float(h2));
            Al[r][kq * 4 + 3] = __float2bfloat16_rn(av.w - __bfloat162float(h3));
        }
#pragma unroll
        for (int t = 0; t < 2; t++) {
            int li = tid + t * 256;
            int kk = li >> 4, oq = li & 15;
            float4 wv = *(const float4*)(W + (size_t)(k0 + kk) * wld + col0 + oq * 4);
            __nv_bfloat16 h0 = __float2bfloat16_rn(wv.x);
            __nv_bfloat16 h1 = __float2bfloat16_rn(wv.y);
            __nv_bfloat16 h2 = __float2bfloat16_rn(wv.z);
            __nv_bfloat16 h3 = __float2bfloat16_rn(wv.w);
            Wh[oq * 4 + 0][kk] = h0; Wh[oq * 4 + 1][kk] = h1;
            Wh[oq * 4 + 2][kk] = h2; Wh[oq * 4 + 3][kk] = h3;
            Wl[oq * 4 + 0][kk] = __float2bfloat16_rn(wv.x - __bfloat162float(h0));
            Wl[oq * 4 + 1][kk] = __float2bfloat16_rn(wv.y - __bfloat162float(h1));
            Wl[oq * 4 + 2][kk] = __float2bfloat16_rn(wv.z - __bfloat162float(h2));
            Wl[oq * 4 + 3][kk] = __float2bfloat16_rn(wv.w - __bfloat162float(h3));
        }
        __syncthreads();
#pragma unroll
        for (int ks = 0; ks < 2; ks++) {
            int kb = ks * 16;
            uint32_t ah[2][4], al[2][4];
#pragma unroll
            for (int mt = 0; mt < 2; mt++) {
                int ar = warpM * 32 + mt * 16 + gid;
                ah[mt][0] = *(const uint32_t*)&Ah[ar][kb + 2 * tig];
                ah[mt][1] = *(const uint32_t*)&Ah[ar + 8][kb + 2 * tig];
                ah[mt][2] = *(const uint32_t*)&Ah[ar][kb + 2 * tig + 8];
                ah[mt][3] = *(const uint32_t*)&Ah[ar + 8][kb + 2 * tig + 8];
                al[mt][0] = *(const uint32_t*)&Al[ar][kb + 2 * tig];
                al[mt][1] = *(const uint32_t*)&Al[ar + 8][kb + 2 * tig];
                al[mt][2] = *(const uint32_t*)&Al[ar][kb + 2 * tig + 8];
                al[mt][3] = *(const uint32_t*)&Al[ar + 8][kb + 2 * tig + 8];
            }
            uint32_t bh[4][2], bl[4][2];
#pragma unroll
            for (int nt = 0; nt < 4; nt++) {
                int bc = warpN * 32 + nt * 8 + gid;
                bh[nt][0] = *(const uint32_t*)&Wh[bc][kb + 2 * tig];
                bh[nt][1] = *(const uint32_t*)&Wh[bc][kb + 2 * tig + 8];
                bl[nt][0] = *(const uint32_t*)&Wl[bc][kb + 2 * tig];
                bl[nt][1] = *(const uint32_t*)&Wl[bc][kb + 2 * tig + 8];
            }
#pragma unroll
            for (int mt = 0; mt < 2; mt++)
#pragma unroll
                for (int nt = 0; nt < 4; nt++) {
                    mma16(acc[mt][nt], ah[mt][0], ah[mt][1], ah[mt][2], ah[mt][3],
                          bl[nt][0], bl[nt][1]);
                    mma16(acc[mt][nt], al[mt][0], al[mt][1], al[mt][2], al[mt][3],
                          bh[nt][0], bh[nt][1]);
                    mma16(acc[mt][nt], ah[mt][0], ah[mt][1], ah[mt][2], ah[mt][3],
                          bh[nt][0], bh[nt][1]);
                }
        }
        __syncthreads();
    }
#pragma unroll
    for (int mt = 0; mt < 2; mt++) {
        int rl = r0 + warpM * 32 + mt * 16 + gid;
#pragma unroll
        for (int half = 0; half < 2; half++) {
            int row = rl + half * 8;
            if (row >= rows) continue;
#pragma unroll
            for (int nt = 0; nt < 4; nt++) {
                int col = col0 + warpN * 32 + nt * 8 + tig * 2;
                float v0 = acc[mt][nt][half * 2 + 0];
                float v1 = acc[mt][nt][half * 2 + 1];
                if (bias) { v0 += bias[col]; v1 += bias[col + 1]; }
                if (ACT == 1) {
                    v0 = (v0 > 0.f) ? v0 : 0.01f * v0;
                    v1 = (v1 > 0.f) ? v1 : 0.01f * v1;
                }
                float2* cp = (float2*)(C + (size_t)row * ldc + col);
                if (ACCUM) { float2 o = *cp; v0 += o.x; v1 += o.y; }
                *cp = make_float2(v0, v1);
            }
        }
    }
}

// ---------------- outputs ----------------
__global__ void k_glob_sum(const int* __restrict__ batch) {
    int idx = blockIdx.x * blockDim.x + threadIdx.x;
    if (idx >= NN * D64) return;
    atomicAdd(&g_gsum[batch[idx >> 6] * D64 + (idx & 63)], g_h[idx]);
}

__global__ void k_glob_out(float* __restrict__ out) {
    int idx = blockIdx.x * blockDim.x + threadIdx.x;
    if (idx >= GG * D64) return;
    int g = idx >> 6;
    out[NN * D64 + idx] = g_gsum[idx] / fmaxf(g_cntn[g], 1.f) + g_h[NN * D64 + idx];
}

__global__ void k_ne_out(const int* __restrict__ ne0, const int* __restrict__ ne1,
                         float* __restrict__ out) {
    int idx = blockIdx.x * blockDim.x + threadIdx.x;
    if (idx >= NE_ * D64) return;
    int j = idx >> 6, d = idx & 63;
    out[(NN + GG) * D64 + idx] = g_h[ne0[j] * D64 + d] + g_h[ne1[j] * D64 + d];
}

__global__ void k_cleanup() {
    int idx = blockIdx.x * blockDim.x + threadIdx.x;
    if (idx < GG * D64) g_gsum[idx] = 0.f;
    if (idx < GG) g_cntn[idx] = 0.f;
}

// ---------------- host launcher ----------------
#define GETSYM(ptr, sym) do { void* _p; cudaGetSymbolAddress(&_p, sym); ptr = (decltype(ptr))_p; } while (0)

extern "C" void kernel_launch(void* const* d_in, const int* in_sizes, int n_in,
                              void* d_out, int out_size) {
    const float* x          = (const float*)d_in[0];
    const float* cond       = (const float*)d_in[1];
    const float* edge_attr  = (const float*)d_in[2];
    const int*   edge_index = (const int*)d_in[3];
    const int*   ne_index   = (const int*)d_in[4];
    const int*   batch      = (const int*)d_in[5];
    const float* gen_w  = (const float*)d_in[6];
    const float* gen_b  = (const float*)d_in[7];
    const float* q_w    = (const float*)d_in[8];
    const float* q_b    = (const float*)d_in[9];
    const float* k_w    = (const float*)d_in[10];
    const float* k_b    = (const float*)d_in[11];
    const float* v_w    = (const float*)d_in[12];
    const float* v_b    = (const float*)d_in[13];
    const float* e_w    = (const float*)d_in[14];
    const float* skip_w = (const float*)d_in[15];
    const float* skip_b = (const float*)d_in[16];
    const float* lin_w  = (const float*)d_in[17];
    const float* lin_b  = (const float*)d_in[18];
    const float* ff_w1  = (const float*)d_in[19];
    const float* ff_b1  = (const float*)d_in[20];
    const float* ff_w2  = (const float*)d_in[21];
    const float* ff_b2  = (const float*)d_in[22];
    float* out = (float*)d_out;

    float *h_p, *big_p, *qkvp_p, *lh_p, *ln2_p, *ffh_p;
    float *w2_p, *w3_p, *qpw_p, *swlw_p, *lw3_p, *wcat_p, *wlin_p;
    float *wcat2_p, *bcat2_p, *wlin2_p, *blb2_p;
    GETSYM(h_p, g_h);
    GETSYM(big_p, g_big);   GETSYM(qkvp_p, g_qkvp); GETSYM(lh_p, g_lh);
    GETSYM(ln2_p, g_ln2);   GETSYM(ffh_p, g_ffh);
    GETSYM(w2_p, g_w2);     GETSYM(w3_p, g_w3);     GETSYM(qpw_p, g_qpw);
    GETSYM(swlw_p, g_swlw); GETSYM(lw3_p, g_lw3);   GETSYM(wcat_p, g_wcat);
    GETSYM(wlin_p, g_wlin);
    GETSYM(wcat2_p, g_wcat2); GETSYM(bcat2_p, g_bcat2);
    GETSYM(wlin2_p, g_wlin2); GETSYM(blb2_p, g_blb2);

    const int T = 256;
    const int GRID_N = CDIV(NAUG, 128);
    cudaStream_t st = 0;

    // ---- setup ----
    k_build_edges<<<CDIV(MM, T), T, 0, st>>>(edge_index, edge_index + EE, batch);
    k_scanA<<<NB_SCAN, 256, 0, st>>>();
    k_scanB<<<1, 256, 0, st>>>();
    k_scanC<<<NB_SCAN, 256, 0, st>>>();
    k_scatter<<<CDIV(MM, T), T, 0, st>>>();
    k_abatch<<<CDIV(NAUG, T), T, 0, st>>>(batch);
    k_cntn<<<CDIV(NN, T), T, 0, st>>>(batch);
    k_init_h<<<CDIV(NAUG * D64, T), T, 0, st>>>(x, cond);
    k_tail_ep<<<CDIV(2 * NN * D64, T), T, 0, st>>>();
    k_tail_csr<<<CDIV(NAUG * 32, T), T, 0, st>>>(edge_attr);
    k_eperm<<<CDIV(MM * 32, T), T, 0, st>>>(edge_attr);

    // ---- layers ----
    for (int i = 0; i < LL; i++) {
        const float* gw  = gen_w  + (size_t)i * D64 * D64;
        const float* gb  = gen_b  + (size_t)i * D64;
        const float* qw  = q_w    + (size_t)i * HD * HD;
        const float* qb  = q_b    + (size_t)i * HD;
        const float* kw  = k_w    + (size_t)i * HD * HD;
        const float* kb  = k_b    + (size_t)i * HD;
        const float* vw  = v_w    + (size_t)i * HD * HD;
        const float* vb  = v_b    + (size_t)i * HD;
        const float* ew  = e_w    + (size_t)i * D64 * HD;
        const float* sw  = skip_w + (size_t)i * HD * HD;
        const float* sb  = skip_b + (size_t)i * HD;
        const float* lw  = lin_w  + (size_t)i * HD * D64;
        const float* lb  = lin_b  + (size_t)i * D64;
        const float* f1w = ff_w1  + (size_t)i * D64 * 4 * D64;
        const float* f1b = ff_b1  + (size_t)i * 4 * D64;
        const float* f2w = ff_w2  + (size_t)i * 4 * D64 * D64;
        const float* f2b = ff_b2  + (size_t)i * D64;

        // weight precomputes (fp32, tiny)
        k_build_w2<<<CDIV(HD * HD, T), T, 0, st>>>(ew);
        k_build_w3<<<CDIV(HD * HD, T), T, 0, st>>>(ew);
        k_gemm2<HD, HD, 0, 0><<<dim3(1, 1), T, 0, st>>>(qw, w2_p, nullptr, qpw_p, HD, HD, HD);
        k_gemm2<HD, D64, 0, 0><<<dim3(1, 1), T, 0, st>>>(sw, lw, nullptr, swlw_p, D64, HD, D64);
        k_gemm2<HD, D64, 0, 0><<<dim3(1, 1), T, 0, st>>>(w3_p, lw, nullptr, lw3_p, D64, HD, D64);
        k_biaslin<<<1, 64, 0, st>>>(sb, lw, lb);
        k_wcat<<<CDIV(HD * 512, T), T, 0, st>>>(qw, kw, vw);
        k_bcat<<<2, 256, 0, st>>>(qb, kb, vb);
        k_wlin<<<CDIV(384 * D64, T), T, 0, st>>>(lw);
        // gen-GEMM fold: wcat2/wlin2 bottom = gw @ (wcat/wlin)[64:128], tops copied
        k_gemm2<D64, HD, 0, 0><<<dim3(1, 4), T, 0, st>>>(gw, wcat_p + 64 * 512, nullptr,
                                                         wcat2_p + 64 * 512, 512, 64, 512);
        k_gemm2<D64, D64, 0, 0><<<dim3(1, 1), T, 0, st>>>(gw, wlin_p + 64 * 64, nullptr,
                                                          wlin2_p + 64 * 64, 64, 64, 64);
        k_fold_copy<<<CDIV(64 * 512 + 64 * 64 + 256 * 64, T), T, 0, st>>>();
        k_fold_bias<<<CDIV(512 + 64, T), T, 0, st>>>(gb);

        // LN1 -> hn + big[:, :64]
        k_ln_stats<<<CDIV(NAUG * 32, T), T, 0, st>>>(h_p);
        k_ln_final<<<1, GG, 0, st>>>();
        k_ln_apply2<<<CDIV(NAUG * D64, T), T, 0, st>>>(h_p);

        // gen_conv -> big[:, 64:128] (raw relu-sum + hn; GEMM folded into weights)
        k_gen<<<CDIV(NN * 32, T), T, 0, st>>>();
        k_gen_v<<<GG, T, 0, st>>>();

        // fused q|k|v|qp projection from [hn|geno]
        k_gemm_bf<0, 0><<<dim3(GRID_N, 8), T, 0, st>>>(big_p, 384, wcat2_p, 512, bcat2_p,
                                                       qkvp_p, 512, NAUG, HD);

        // fused single-pass attention -> big[:, 128:256] (t), big[:, 256:384] (we)
        k_attn<<<CDIV(NN * 32, T), T, 0, st>>>();
        k_attn_v<<<GG, T, 0, st>>>();

        // lh = big @ wlin2 + blb2
        k_gemm_bf<0, 0><<<dim3(GRID_N, 1), T, 0, st>>>(big_p, 384, wlin2_p, D64, blb2_p,
                                                       lh_p, D64, NAUG, 384);

        // LN2
        k_ln_stats<<<CDIV(NAUG * 32, T), T, 0, st>>>(lh_p);
        k_ln_final<<<1, GG, 0, st>>>();
        k_ln_apply<<<CDIV(NAUG * D64, T), T, 0, st>>>(lh_p, ln2_p);

        // FF + residual
        k_gemm_bf<1, 0><<<dim3(GRID_N, 4), T, 0, st>>>(ln2_p, D64, f1w, 256, f1b,
                                                       ffh_p, 256, NAUG, D64);
        k_gemm_bf<0, 1><<<dim3(GRID_N, 1), T, 0, st>>>(ffh_p, 256, f2w, D64, f2b,
                                                       h_p, D64, NAUG, 256);
    }

    // ---- outputs ----
    cudaMemcpyAsync(out, h_p, sizeof(float) * NN * D64, cudaMemcpyDeviceToDevice, st);
    k_glob_sum<<<CDIV(NN * D64, T), T, 0, st>>>(batch);
    k_glob_out<<<CDIV(GG * D64, T), T, 0, st>>>(out);
    k_ne_out<<<CDIV(NE_ * D64, T), T, 0, st>>>(ne_index, ne_index + NE_, out);
    k_cleanup<<<CDIV(GG * D64, T), T, 0, st>>>();
}

// round 9
// speedup vs baseline: 1.1235x; 1.0999x over previous
#include <cuda_runtime.h>
#include <cuda_bf16.h>
#include <math.h>
#include <stdint.h>

// Problem constants
#define D64   64
#define HH    2
#define HD    128
#define LL    3
#define NN    50000
#define GG    128
#define EE    600000
#define NE_   300000
#define NAUG  (NN + GG)          // 50128
#define M0    (EE + 2 * NN)      // 700000
#define MM    (M0 + NAUG)        // 750128
#define TAILR (MM - EE)          // 150128
#define NB_SCAN ((NAUG + 255) / 256)   // 196

#define CDIV(a, b) (((a) + (b) - 1) / (b))

// ---------------- device scratch (static, no allocs) ----------------
__device__ int    g_src[MM];
__device__ int    g_dst[MM];
__device__ int    g_deg[NAUG];
__device__ int    g_rowptr[NAUG + 1];
__device__ int    g_bsum[256];
__device__ int    g_fill[NAUG];
__device__ int    g_esrc[MM];
__device__ int    g_eid[MM];
__device__ float  g_eperm[(size_t)MM * D64];     // e_aug rows in CSR order
__device__ float  g_tail[(size_t)TAILR * D64];   // e_aug rows >= EE
__device__ float  g_h[NAUG * D64];
__device__ float  g_hn[NAUG * D64];
__device__ float  g_big[(size_t)NAUG * 384];     // [hn(64)|geno(64) | t(128) | we(128)]
__device__ float  g_qkvp[(size_t)NAUG * 512];    // [q | k | v | qp]
__device__ float  g_lh[NAUG * D64];
__device__ float  g_ffh[(size_t)NAUG * 256];
// per-layer precomputed weights
__device__ float  g_qpw[LL][HD * HD];
__device__ float  g_swlw[LL][HD * D64];
__device__ float  g_lw3[LL][HD * D64];
__device__ float  g_blb[LL][D64];
__device__ float  g_wcat2[LL][HD * 512];
__device__ float  g_bcat2[LL][512];
__device__ float  g_wlin2[LL][384 * D64];
__device__ float  g_blb2[LL][D64];
// LN / misc
__device__ float  g_cntn[GG];
__device__ double g_lsum[GG];
__device__ double g_lsumsq[GG];
__device__ float  g_mean[GG];
__device__ float  g_rstd[GG];
__device__ int    g_abatch[NAUG];
__device__ float  g_gsum[GG * D64];

// ---------------- setup kernels ----------------
__global__ void k_build_edges(const int* __restrict__ ei0, const int* __restrict__ ei1,
                              const int* __restrict__ batch) {
    int m = blockIdx.x * blockDim.x + threadIdx.x;
    if (m >= MM) return;
    int s, d;
    if (m < EE)               { s = ei0[m]; d = ei1[m]; }
    else if (m < EE + NN)     { int i = m - EE;          s = i;             d = batch[i] + NN; }
    else if (m < EE + 2 * NN) { int i = m - EE - NN;     s = batch[i] + NN; d = i; }
    else                      { int i = m - EE - 2 * NN; s = i;             d = i; }
    g_src[m] = s; g_dst[m] = d;
    atomicAdd(&g_deg[d], 1);
}

__global__ void k_scanA() {
    __shared__ int sh[256];
    int t = threadIdx.x;
    int i = blockIdx.x * 256 + t;
    int v = (i < NAUG) ? g_deg[i] : 0;
    sh[t] = v;
    __syncthreads();
    for (int off = 1; off < 256; off <<= 1) {
        int a = (t >= off) ? sh[t - off] : 0;
        __syncthreads();
        sh[t] += a;
        __syncthreads();
    }
    if (i < NAUG) g_rowptr[i] = sh[t] - v;
    if (t == 255) g_bsum[blockIdx.x] = sh[255];
}

__global__ void k_scanB() {
    __shared__ int sh[256];
    int t = threadIdx.x;
    int v = (t < NB_SCAN) ? g_bsum[t] : 0;
    sh[t] = v;
    __syncthreads();
    for (int off = 1; off < 256; off <<= 1) {
        int a = (t >= off) ? sh[t - off] : 0;
        __syncthreads();
        sh[t] += a;
        __syncthreads();
    }
    if (t < NB_SCAN) g_bsum[t] = sh[t] - v;
}

__global__ void k_scanC() {
    int i = blockIdx.x * 256 + threadIdx.x;
    if (i < NAUG) {
        int r = g_rowptr[i] + g_bsum[i >> 8];
        g_rowptr[i] = r;
        g_fill[i] = r;
        g_deg[i] = 0;                 // self-clean
    }
    if (i == 0) g_rowptr[NAUG] = MM;
}

__global__ void k_scatter() {
    int m = blockIdx.x * blockDim.x + threadIdx.x;
    if (m >= MM) return;
    int pos = atomicAdd(&g_fill[g_dst[m]], 1);
    g_esrc[pos] = g_src[m];
    g_eid[pos]  = m;
}

// fused misc setup: init h, e_p tail rows, abatch, cntn
__global__ void k_misc(const float* __restrict__ x, const float* __restrict__ cond,
                       const int* __restrict__ batch) {
    int idx = blockIdx.x * blockDim.x + threadIdx.x;
    if (idx < NAUG * D64)
        g_h[idx] = (idx < NN * D64) ? x[idx] : cond[idx - NN * D64];
    if (idx < 2 * NN * D64)
        g_tail[idx] = ((idx & 63) == 0) ? 1.f : 0.f;
    if (idx < NAUG)
        g_abatch[idx] = (idx < NN) ? batch[idx] : (idx - NN);
    if (idx < NN)
        atomicAdd(&g_cntn[batch[idx]], 1.f);
}

__global__ void k_tail_csr(const float* __restrict__ edge_attr) {
    int i = (blockIdx.x * blockDim.x + threadIdx.x) >> 5;
    int lane = threadIdx.x & 31;
    if (i >= NAUG) return;
    float2 acc = {0.f, 0.f};
    float cnt = 0.f;
    int e0 = g_rowptr[i], e1 = g_rowptr[i + 1];
    for (int e = e0; e < e1; e++) {
        int m = g_eid[e];
        if (m < EE) {
            float2 ev = ((const float2*)(edge_attr + (size_t)m * D64))[lane];
            acc.x += ev.x; acc.y += ev.y;
            cnt += 1.f;
        } else if (m < M0) {
            if (lane == 0) acc.x += 1.f;
            cnt += 1.f;
        }
    }
    float invc = 1.f / fmaxf(cnt, 1.f);
    float2 o = {acc.x * invc, acc.y * invc};
    ((float2*)(g_tail + (size_t)(2 * NN + i) * D64))[lane] = o;
}

__global__ void k_eperm(const float* __restrict__ edge_attr) {
    int gw = (blockIdx.x * blockDim.x + threadIdx.x) >> 5;
    int lane = threadIdx.x & 31;
    if (gw >= MM) return;
    int m = g_eid[gw];
    const float* ep = (m < EE) ? edge_attr + (size_t)m * D64
                               : g_tail + (size_t)(m - EE) * D64;
    float2 v = ((const float2*)ep)[lane];
    ((float2*)(g_eperm + (size_t)gw * D64))[lane] = v;
}

// ---------------- batched weight prep (all layers, 2 kernels) ----------------
// prep1: qpw = qw@W2 (W2 inlined from ew), swlw = sw@lw, lw3 = W3@lw, blb = lb + sb@lw
#define P1_PER (128 * 128 + 128 * 64 + 128 * 64 + 64)   // 32832
__global__ void k_prep1(const float* __restrict__ qw_all, const float* __restrict__ ew_all,
                        const float* __restrict__ sw_all, const float* __restrict__ lw_all,
                        const float* __restrict__ sb_all, const float* __restrict__ lb_all) {
    int idx = blockIdx.x * blockDim.x + threadIdx.x;
    int l = idx / P1_PER, j = idx % P1_PER;
    if (l >= LL) return;
    const float* qw = qw_all + (size_t)l * HD * HD;
    const float* ew = ew_all + (size_t)l * D64 * HD;
    const float* sw = sw_all + (size_t)l * HD * HD;
    const float* lw = lw_all + (size_t)l * HD * D64;
    const float* sb = sb_all + (size_t)l * HD;
    const float* lb = lb_all + (size_t)l * D64;
    if (j < 128 * 128) {                       // qpw[x][o=h*64+c]
        int xx = j >> 7, o = j & 127;
        int h = o >> 6, c = o & 63;
        float a = 0.f;
        for (int d = 0; d < 64; d++) a += qw[xx * HD + h * 64 + d] * ew[c * HD + h * 64 + d];
        g_qpw[l][j] = a;
    } else if (j < 128 * 128 + 128 * 64) {     // swlw
        int jj = j - 128 * 128;
        int r = jj >> 6, u = jj & 63;
        float a = 0.f;
        for (int k2 = 0; k2 < 128; k2++) a += sw[r * HD + k2] * lw[k2 * D64 + u];
        g_swlw[l][jj] = a;
    } else if (j < 128 * 128 + 2 * 128 * 64) { // lw3[r=h*64+c][u]
        int jj = j - 128 * 128 - 128 * 64;
        int r = jj >> 6, u = jj & 63;
        int h = r >> 6, c = r & 63;
        float a = 0.f;
        for (int o2 = 0; o2 < 64; o2++)
            a += ew[c * HD + h * 64 + o2] * lw[(h * 64 + o2) * D64 + u];
        g_lw3[l][jj] = a;
    } else {                                   // blb
        int o = j - 128 * 128 - 2 * 128 * 64;
        float a = lb[o];
        for (int k2 = 0; k2 < 128; k2++) a += sb[k2] * lw[k2 * D64 + o];
        g_blb[l][o] = a;
    }
}

__device__ __forceinline__ float wcat_row(const float* qw, const float* kw,
                                          const float* vw, const float* qpw,
                                          int r, int c) {
    if (c < 128) return qw[r * HD + c];
    if (c < 256) return kw[r * HD + c - 128];
    if (c < 384) return vw[r * HD + c - 256];
    return qpw[r * HD + c - 384];
}

// prep2: folded weights wcat2, wlin2, bcat2, blb2
#define P2_PER (128 * 512 + 384 * 64 + 512 + 64)   // 90688
__global__ void k_prep2(const float* __restrict__ qw_all, const float* __restrict__ kw_all,
                        const float* __restrict__ vw_all, const float* __restrict__ ew_all,
                        const float* __restrict__ gw_all, const float* __restrict__ gb_all,
                        const float* __restrict__ qb_all, const float* __restrict__ kb_all,
                        const float* __restrict__ vb_all, const float* __restrict__ lw_all) {
    int idx = blockIdx.x * blockDim.x + threadIdx.x;
    int l = idx / P2_PER, j = idx % P2_PER;
    if (l >= LL) return;
    const float* qw = qw_all + (size_t)l * HD * HD;
    const float* kw = kw_all + (size_t)l * HD * HD;
    const float* vw = vw_all + (size_t)l * HD * HD;
    const float* ew = ew_all + (size_t)l * D64 * HD;
    const float* gw = gw_all + (size_t)l * D64 * D64;
    const float* gb = gb_all + (size_t)l * D64;
    const float* qb = qb_all + (size_t)l * HD;
    const float* kb = kb_all + (size_t)l * HD;
    const float* vb = vb_all + (size_t)l * HD;
    const float* lw = lw_all + (size_t)l * HD * D64;
    const float* qpw = g_qpw[l];
    if (j < 128 * 512) {                               // wcat2
        int r = j >> 9, c = j & 511;
        float v;
        if (r < 64) v = wcat_row(qw, kw, vw, qpw, r, c);
        else {
            int d = r - 64;
            float a = 0.f;
            for (int t = 0; t < 64; t++) a += gw[d * 64 + t] * wcat_row(qw, kw, vw, qpw, 64 + t, c);
            v = a;
        }
        g_wcat2[l][j] = v;
    } else if (j < 128 * 512 + 384 * 64) {             // wlin2
        int jj = j - 128 * 512;
        int r = jj >> 6, u = jj & 63;
        float v;
        if (r < 64) v = g_swlw[l][r * 64 + u];
        else if (r < 128) {
            int d = r - 64;
            float a = 0.f;
            for (int t = 0; t < 64; t++) a += gw[d * 64 + t] * g_swlw[l][(64 + t) * 64 + u];
            v = a;
        } else if (r < 256) v = lw[(size_t)(r - 128) * D64 + u];
        else v = g_lw3[l][(r - 256) * 64 + u];
        g_wlin2[l][jj] = v;
    } else if (j < 128 * 512 + 384 * 64 + 512) {       // bcat2
        int c = j - (128 * 512 + 384 * 64);
        float base;
        if (c < 128)      base = qb[c];
        else if (c < 256) base = kb[c - 128];
        else if (c < 384) base = vb[c - 256];
        else {
            int o = c - 384, h = o >> 6, cc = o & 63;
            float a = 0.f;
            for (int d = 0; d < 64; d++) a += qb[h * 64 + d] * ew[cc * HD + h * 64 + d];
            base = a;
        }
        float a = base;
        for (int t = 0; t < 64; t++) a += gb[t] * wcat_row(qw, kw, vw, qpw, 64 + t, c);
        g_bcat2[l][c] = a;
    } else {                                           // blb2
        int u = j - (128 * 512 + 384 * 64 + 512);
        float a = g_blb[l][u];
        for (int t = 0; t < 64; t++) a += gb[t] * g_swlw[l][(64 + t) * 64 + u];
        g_blb2[l][u] = a;
    }
}

// ---------------- graph layernorm ----------------
__global__ void k_ln_stats(const float* __restrict__ X) {
    int i = (blockIdx.x * blockDim.x + threadIdx.x) >> 5;
    int lane = threadIdx.x & 31;
    if (i >= NAUG) return;
    float2 v = ((const float2*)(X + (size_t)i * D64))[lane];
    float s  = v.x + v.y;
    float ss = v.x * v.x + v.y * v.y;
#pragma unroll
    for (int off = 16; off; off >>= 1) {
        s  += __shfl_xor_sync(0xffffffffu, s, off);
        ss += __shfl_xor_sync(0xffffffffu, ss, off);
    }
    if (lane == 0) {
        int b = g_abatch[i];
        atomicAdd(&g_lsum[b], (double)s);
        atomicAdd(&g_lsumsq[b], (double)ss);
    }
}

__global__ void k_ln_final() {
    int g = threadIdx.x;
    if (g >= GG) return;
    double norm = (double)fmaxf(g_cntn[g] + 1.f, 1.f) * D64;
    double mean = g_lsum[g] / norm;
    double var  = g_lsumsq[g] / norm - mean * mean;
    g_mean[g] = (float)mean;
    g_rstd[g] = rsqrtf((float)var + 1e-5f);
    g_lsum[g] = 0.0;            // self-clean
    g_lsumsq[g] = 0.0;
}

// writes hn AND big[:, 0:64]
__global__ void k_ln_apply2(const float* __restrict__ X) {
    int idx = blockIdx.x * blockDim.x + threadIdx.x;
    if (idx >= NAUG * D64) return;
    int i = idx >> 6, d = idx & 63;
    int b = g_abatch[i];
    float v = (X[idx] - g_mean[b]) * g_rstd[b];
    g_hn[idx] = v;
    g_big[(size_t)i * 384 + d] = v;
}

// ---------------- gen_conv ----------------
__global__ void k_gen() {
    int i = (blockIdx.x * blockDim.x + threadIdx.x) >> 5;
    int lane = threadIdx.x & 31;
    if (i >= NN) return;
    float2 acc = {0.f, 0.f};
    int e0 = g_rowptr[i], e1 = g_rowptr[i + 1];
    for (int e = e0; e < e1; e++) {
        int s = g_esrc[e];
        float2 ev = ((const float2*)(g_eperm + (size_t)e * D64))[lane];
        float2 hv = ((const float2*)(g_hn + (size_t)s * D64))[lane];
        acc.x += fmaxf(hv.x + ev.x, 0.f) + 1e-7f;
        acc.y += fmaxf(hv.y + ev.y, 0.f) + 1e-7f;
    }
    float2 hi = ((const float2*)(g_hn + (size_t)i * D64))[lane];
    float2 o = {acc.x + hi.x, acc.y + hi.y};
    ((float2*)(g_big + (size_t)i * 384 + 64))[lane] = o;
}

__global__ void k_gen_v() {
    __shared__ float sa[64];
    int i = NN + blockIdx.x;
    int tid = threadIdx.x, lane = tid & 31, wid = tid >> 5;
    if (tid < 64) sa[tid] = 0.f;
    __syncthreads();
    int e0 = g_rowptr[i], e1 = g_rowptr[i + 1];
    float2 acc = {0.f, 0.f};
    for (int e = e0 + wid; e < e1; e += 8) {
        int s = g_esrc[e];
        float2 ev = ((const float2*)(g_eperm + (size_t)e * D64))[lane];
        float2 hv = ((const float2*)(g_hn + (size_t)s * D64))[lane];
        acc.x += fmaxf(hv.x + ev.x, 0.f) + 1e-7f;
        acc.y += fmaxf(hv.y + ev.y, 0.f) + 1e-7f;
    }
    atomicAdd(&sa[2 * lane],     acc.x);
    atomicAdd(&sa[2 * lane + 1], acc.y);
    __syncthreads();
    if (tid < 64) g_big[(size_t)i * 384 + 64 + tid] = sa[tid] + g_hn[(size_t)i * D64 + tid];
}

// ---------------- fused single-pass attention (online softmax) ----------------
__global__ void k_attn() {
    int i = (blockIdx.x * blockDim.x + threadIdx.x) >> 5;
    int lane = threadIdx.x & 31;
    if (i >= NN) return;
    int el = lane & 15;
    float4 q4  = *(const float4*)(g_qkvp + (size_t)i * 512 + 4 * lane);
    float4 qp4 = *(const float4*)(g_qkvp + (size_t)i * 512 + 384 + 4 * lane);
    int e0 = g_rowptr[i], e1 = g_rowptr[i + 1];
    float mx = -INFINITY, sum = 0.f;
    float4 vacc = {0.f, 0.f, 0.f, 0.f};
    float4 eacc = {0.f, 0.f, 0.f, 0.f};
    for (int e = e0; e < e1; e++) {
        int s = g_esrc[e];
        const float* ep = g_eperm + (size_t)e * D64;
        float4 k4 = *(const float4*)(g_qkvp + (size_t)s * 512 + 128 + 4 * lane);
        float4 e4 = *(const float4*)(ep + 4 * el);
        float p = q4.x * k4.x + q4.y * k4.y + q4.z * k4.z + q4.w * k4.w
                + qp4.x * e4.x + qp4.y * e4.y + qp4.z * e4.z + qp4.w * e4.w;
        p += __shfl_xor_sync(0xffffffffu, p, 1);
        p += __shfl_xor_sync(0xffffffffu, p, 2);
        p += __shfl_xor_sync(0xffffffffu, p, 4);
        p += __shfl_xor_sync(0xffffffffu, p, 8);
        float a = p * 0.125f;
        if (a > mx) {
            float sc = expf(mx - a);
            sum *= sc;
            vacc.x *= sc; vacc.y *= sc; vacc.z *= sc; vacc.w *= sc;
            eacc.x *= sc; eacc.y *= sc; eacc.z *= sc; eacc.w *= sc;
            mx = a;
        }
        float w = expf(a - mx);
        sum += w;
        float4 v4 = *(const float4*)(g_qkvp + (size_t)s * 512 + 256 + 4 * lane);
        vacc.x += w * v4.x; vacc.y += w * v4.y; vacc.z += w * v4.z; vacc.w += w * v4.w;
        eacc.x += w * e4.x; eacc.y += w * e4.y; eacc.z += w * e4.z; eacc.w += w * e4.w;
    }
    float inv = 1.f / (sum + 1e-16f);
    float4 to = {vacc.x * inv, vacc.y * inv, vacc.z * inv, vacc.w * inv};
    float4 wo = {eacc.x * inv, eacc.y * inv, eacc.z * inv, eacc.w * inv};
    *(float4*)(g_big + (size_t)i * 384 + 128 + 4 * lane) = to;
    *(float4*)(g_big + (size_t)i * 384 + 256 + 4 * lane) = wo;
}

__global__ void k_attn_v() {
    __shared__ float sv[128];
    __shared__ float se[128];
    __shared__ float ssg[2];
    __shared__ float swmx[16];
    __shared__ float gmx[2];
    int i = NN + blockIdx.x;
    int tid = threadIdx.x, lane = tid & 31, wid = tid >> 5;
    int el = lane & 15;
    int hh = lane >> 4;
    if (tid < 128) { sv[tid] = 0.f; se[tid] = 0.f; }
    if (tid < 2) ssg[tid] = 0.f;
    __syncthreads();
    float4 q4  = *(const float4*)(g_qkvp + (size_t)i * 512 + 4 * lane);
    float4 qp4 = *(const float4*)(g_qkvp + (size_t)i * 512 + 384 + 4 * lane);
    int e0 = g_rowptr[i], e1 = g_rowptr[i + 1];
    float mx = -INFINITY, sum = 0.f;
    float4 vacc = {0.f, 0.f, 0.f, 0.f};
    float4 eacc = {0.f, 0.f, 0.f, 0.f};
    for (int e = e0 + wid; e < e1; e += 8) {
        int s = g_esrc[e];
        const float* ep = g_eperm + (size_t)e * D64;
        float4 k4 = *(const float4*)(g_qkvp + (size_t)s * 512 + 128 + 4 * lane);
        float4 e4 = *(const float4*)(ep + 4 * el);
        float p = q4.x * k4.x + q4.y * k4.y + q4.z * k4.z + q4.w * k4.w
                + qp4.x * e4.x + qp4.y * e4.y + qp4.z * e4.z + qp4.w * e4.w;
        p += __shfl_xor_sync(0xffffffffu, p, 1);
        p += __shfl_xor_sync(0xffffffffu, p, 2);
        p += __shfl_xor_sync(0xffffffffu, p, 4);
        p += __shfl_xor_sync(0xffffffffu, p, 8);
        float a = p * 0.125f;
        if (a > mx) {
            float sc = expf(mx - a);
            sum *= sc;
            vacc.x *= sc; vacc.y *= sc; vacc.z *= sc; vacc.w *= sc;
            eacc.x *= sc; eacc.y *= sc; eacc.z *= sc; eacc.w *= sc;
            mx = a;
        }
        float w = expf(a - mx);
        sum += w;
        float4 v4 = *(const float4*)(g_qkvp + (size_t)s * 512 + 256 + 4 * lane);
        vacc.x += w * v4.x; vacc.y += w * v4.y; vacc.z += w * v4.z; vacc.w += w * v4.w;
        eacc.x += w * e4.x; eacc.y += w * e4.y; eacc.z += w * e4.z; eacc.w += w * e4.w;
    }
    if (el == 0) swmx[wid * 2 + hh] = mx;
    __syncthreads();
    if (tid < 2) {
        float m = -INFINITY;
#pragma unroll
        for (int w = 0; w < 8; w++) m = fmaxf(m, swmx[w * 2 + tid]);
        gmx[tid] = m;
    }
    __syncthreads();
    float sc = expf(mx - gmx[hh]);
    atomicAdd(&sv[4 * lane],     vacc.x * sc); atomicAdd(&sv[4 * lane + 1], vacc.y * sc);
    atomicAdd(&sv[4 * lane + 2], vacc.z * sc); atomicAdd(&sv[4 * lane + 3], vacc.w * sc);
    atomicAdd(&se[4 * lane],     eacc.x * sc); atomicAdd(&se[4 * lane + 1], eacc.y * sc);
    atomicAdd(&se[4 * lane + 2], eacc.z * sc); atomicAdd(&se[4 * lane + 3], eacc.w * sc);
    if (el == 0) atomicAdd(&ssg[hh], sum * sc);
    __syncthreads();
    if (tid < 128) {
        float inv = 1.f / (ssg[tid >> 6] + 1e-16f);
        g_big[(size_t)i * 384 + 128 + tid] = sv[tid] * inv;
        g_big[(size_t)i * 384 + 256 + tid] = se[tid] * inv;
    }
}

// ---------------- 3xBF16 tensor-core GEMM (scalar-LDS fragments; optional LN on A) ----------------
__device__ __forceinline__ void mma16(float* c, uint32_t a0, uint32_t a1, uint32_t a2,
                                      uint32_t a3, uint32_t b0, uint32_t b1) {
    asm volatile(
        "mma.sync.aligned.m16n8k16.row.col.f32.bf16.bf16.f32 "
        "{%0,%1,%2,%3}, {%4,%5,%6,%7}, {%8,%9}, {%0,%1,%2,%3};"
        : "+f"(c[0]), "+f"(c[1]), "+f"(c[2]), "+f"(c[3])
        : "r"(a0), "r"(a1), "r"(a2), "r"(a3), "r"(b0), "r"(b1));
}

template <int ACT, int ACCUM, int LNA>
__global__ __launch_bounds__(256) void k_gemm_bf(
        const float* __restrict__ A, int lda,
        const float* __restrict__ W, int wld,
        const float* __restrict__ bias, float* __restrict__ C,
        int ldc, int rows, int K) {
    __shared__ __align__(16) __nv_bfloat16 Ah[128][40];
    __shared__ __align__(16) __nv_bfloat16 Al[128][40];
    __shared__ __align__(16) __nv_bfloat16 Wh[64][40];
    __shared__ __align__(16) __nv_bfloat16 Wl[64][40];
    const int tid = threadIdx.x, lane = tid & 31, warp = tid >> 5;
    const int warpM = warp & 3, warpN = warp >> 2;
    const int gid = lane >> 2, tig = lane & 3;
    const int r0 = blockIdx.x * 128, col0 = blockIdx.y * 64;
    float acc[2][4][4];
#pragma unroll
    for (int mt = 0; mt < 2; mt++)
#pragma unroll
        for (int nt = 0; nt < 4; nt++)
#pragma unroll
            for (int r = 0; r < 4; r++) acc[mt][nt][r] = 0.f;

    for (int k0 = 0; k0 < K; k0 += 32) {
#pragma unroll
        for (int t = 0; t < 4; t++) {
            int li = tid + t * 256;
            int r = li >> 3, kq = li & 7;
            int row = r0 + r;
            float4 av = make_float4(0.f, 0.f, 0.f, 0.f);
            if (row < rows) {
                av = *(const float4*)(A + (size_t)row * lda + k0 + kq * 4);
                if (LNA) {
                    int b = g_abatch[row];
                    float mu = g_mean[b], rs = g_rstd[b];
                    av.x = (av.x - mu) * rs; av.y = (av.y - mu) * rs;
                    av.z = (av.z - mu) * rs; av.w = (av.w - mu) * rs;
                }
            }
            __nv_bfloat16 h0 = __float2bfloat16_rn(av.x);
            __nv_bfloat16 h1 = __float2bfloat16_rn(av.y);
            __nv_bfloat16 h2 = __float2bfloat16_rn(av.z);
            __nv_bfloat16 h3 = __float2bfloat16_rn(av.w);
            Ah[r][kq * 4 + 0] = h0; Ah[r][kq * 4 + 1] = h1;
            Ah[r][kq * 4 + 2] = h2; Ah[r][kq * 4 + 3] = h3;
            Al[r][kq * 4 + 0] = __float2bfloat16_rn(av.x - __bfloat162float(h0));
            Al[r][kq * 4 + 1] = __float2bfloat16_rn(av.y - __bfloat162float(h1));
            Al[r][kq * 4 + 2] = __float2bfloat16_rn(av.z - __bfloat162float(h2));
            Al[r][kq * 4 + 3] = __float2bfloat16_rn(av.w - __bfloat162float(h3));
        }
#pragma unroll
        for (int t = 0; t < 2; t++) {
            int li = tid + t * 256;
            int kk = li >> 4, oq = li & 15;
            float4 wv = *(const float4*)(W + (size_t)(k0 + kk) * wld + col0 + oq * 4);
            __nv_bfloat16 h0 = __float2bfloat16_rn(wv.x);
            __nv_bfloat16 h1 = __float2bfloat16_rn(wv.y);
            __nv_bfloat16 h2 = __float2bfloat16_rn(wv.z);
            __nv_bfloat16 h3 = __float2bfloat16_rn(wv.w);
            Wh[oq * 4 + 0][kk] = h0; Wh[oq * 4 + 1][kk] = h1;
            Wh[oq * 4 + 2][kk] = h2; Wh[oq * 4 + 3][kk] = h3;
            Wl[oq * 4 + 0][kk] = __float2bfloat16_rn(wv.x - __bfloat162float(h0));
            Wl[oq * 4 + 1][kk] = __float2bfloat16_rn(wv.y - __bfloat162float(h1));
            Wl[oq * 4 + 2][kk] = __float2bfloat16_rn(wv.z - __bfloat162float(h2));
            Wl[oq * 4 + 3][kk] = __float2bfloat16_rn(wv.w - __bfloat162float(h3));
        }
        __syncthreads();
#pragma unroll
        for (int ks = 0; ks < 2; ks++) {
            int kb = ks * 16;
            uint32_t ah[2][4], al[2][4];
#pragma unroll
            for (int mt = 0; mt < 2; mt++) {
                int ar = warpM * 32 + mt * 16 + gid;
                ah[mt][0] = *(const uint32_t*)&Ah[ar][kb + 2 * tig];
                ah[mt][1] = *(const uint32_t*)&Ah[ar + 8][kb + 2 * tig];
                ah[mt][2] = *(const uint32_t*)&Ah[ar][kb + 2 * tig + 8];
                ah[mt][3] = *(const uint32_t*)&Ah[ar + 8][kb + 2 * tig + 8];
                al[mt][0] = *(const uint32_t*)&Al[ar][kb + 2 * tig];
                al[mt][1] = *(const uint32_t*)&Al[ar + 8][kb + 2 * tig];
                al[mt][2] = *(const uint32_t*)&Al[ar][kb + 2 * tig + 8];
                al[mt][3] = *(const uint32_t*)&Al[ar + 8][kb + 2 * tig + 8];
            }
            uint32_t bh[4][2], bl[4][2];
#pragma unroll
            for (int nt = 0; nt < 4; nt++) {
                int bc = warpN * 32 + nt * 8 + gid;
                bh[nt][0] = *(const uint32_t*)&Wh[bc][kb + 2 * tig];
                bh[nt][1] = *(const uint32_t*)&Wh[bc][kb + 2 * tig + 8];
                bl[nt][0] = *(const uint32_t*)&Wl[bc][kb + 2 * tig];
                bl[nt][1] = *(const uint32_t*)&Wl[bc][kb + 2 * tig + 8];
            }
#pragma unroll
            for (int mt = 0; mt < 2; mt++)
#pragma unroll
                for (int nt = 0; nt < 4; nt++) {
                    mma16(acc[mt][nt], ah[mt][0], ah[mt][1], ah[mt][2], ah[mt][3],
                          bl[nt][0], bl[nt][1]);
                    mma16(acc[mt][nt], al[mt][0], al[mt][1], al[mt][2], al[mt][3],
                          bh[nt][0], bh[nt][1]);
                    mma16(acc[mt][nt], ah[mt][0], ah[mt][1], ah[mt][2], ah[mt][3],
                          bh[nt][0], bh[nt][1]);
                }
        }
        __syncthreads();
    }
#pragma unroll
    for (int mt = 0; mt < 2; mt++) {
        int rl = r0 + warpM * 32 + mt * 16 + gid;
#pragma unroll
        for (int half = 0; half < 2; half++) {
            int row = rl + half * 8;
            if (row >= rows) continue;
#pragma unroll
            for (int nt = 0; nt < 4; nt++) {
                int col = col0 + warpN * 32 + nt * 8 + tig * 2;
                float v0 = acc[mt][nt][half * 2 + 0];
                float v1 = acc[mt][nt][half * 2 + 1];
                if (bias) { v0 += bias[col]; v1 += bias[col + 1]; }
                if (ACT == 1) {
                    v0 = (v0 > 0.f) ? v0 : 0.01f * v0;
                    v1 = (v1 > 0.f) ? v1 : 0.01f * v1;
                }
                float2* cp = (float2*)(C + (size_t)row * ldc + col);
                if (ACCUM) { float2 o = *cp; v0 += o.x; v1 += o.y; }
                *cp = make_float2(v0, v1);
            }
        }
    }
}

// ---------------- outputs ----------------
__global__ void k_glob_sum(const int* __restrict__ batch) {
    int idx = blockIdx.x * blockDim.x + threadIdx.x;
    if (idx >= NN * D64) return;
    atomicAdd(&g_gsum[batch[idx >> 6] * D64 + (idx & 63)], g_h[idx]);
}

__global__ void k_glob_out(float* __restrict__ out) {
    int idx = blockIdx.x * blockDim.x + threadIdx.x;
    if (idx >= GG * D64) return;
    int g = idx >> 6;
    out[NN * D64 + idx] = g_gsum[idx] / fmaxf(g_cntn[g], 1.f) + g_h[NN * D64 + idx];
}

__global__ void k_ne_out(const int* __restrict__ ne0, const int* __restrict__ ne1,
                         float* __restrict__ out) {
    int idx = blockIdx.x * blockDim.x + threadIdx.x;
    if (idx >= NE_ * D64) return;
    int j = idx >> 6, d = idx & 63;
    out[(NN + GG) * D64 + idx] = g_h[ne0[j] * D64 + d] + g_h[ne1[j] * D64 + d];
}

__global__ void k_cleanup() {
    int idx = blockIdx.x * blockDim.x + threadIdx.x;
    if (idx < GG * D64) g_gsum[idx] = 0.f;
    if (idx < GG) g_cntn[idx] = 0.f;
}

// ---------------- host launcher ----------------
#define GETSYM(ptr, sym) do { void* _p; cudaGetSymbolAddress(&_p, sym); ptr = (decltype(ptr))_p; } while (0)

extern "C" void kernel_launch(void* const* d_in, const int* in_sizes, int n_in,
                              void* d_out, int out_size) {
    const float* x          = (const float*)d_in[0];
    const float* cond       = (const float*)d_in[1];
    const float* edge_attr  = (const float*)d_in[2];
    const int*   edge_index = (const int*)d_in[3];
    const int*   ne_index   = (const int*)d_in[4];
    const int*   batch      = (const int*)d_in[5];
    const float* gen_w  = (const float*)d_in[6];
    const float* gen_b  = (const float*)d_in[7];
    const float* q_w    = (const float*)d_in[8];
    const float* q_b    = (const float*)d_in[9];
    const float* k_w    = (const float*)d_in[10];
    const float* k_b    = (const float*)d_in[11];
    const float* v_w    = (const float*)d_in[12];
    const float* v_b    = (const float*)d_in[13];
    const float* e_w    = (const float*)d_in[14];
    const float* skip_w = (const float*)d_in[15];
    const float* skip_b = (const float*)d_in[16];
    const float* lin_w  = (const float*)d_in[17];
    const float* lin_b  = (const float*)d_in[18];
    const float* ff_w1  = (const float*)d_in[19];
    const float* ff_b1  = (const float*)d_in[20];
    const float* ff_w2  = (const float*)d_in[21];
    const float* ff_b2  = (const float*)d_in[22];
    float* out = (float*)d_out;

    float *h_p, *big_p, *qkvp_p, *lh_p, *ffh_p;
    float *wcat2_p, *bcat2_p, *wlin2_p, *blb2_p;
    GETSYM(h_p, g_h);       GETSYM(big_p, g_big);   GETSYM(qkvp_p, g_qkvp);
    GETSYM(lh_p, g_lh);     GETSYM(ffh_p, g_ffh);
    GETSYM(wcat2_p, g_wcat2); GETSYM(bcat2_p, g_bcat2);
    GETSYM(wlin2_p, g_wlin2); GETSYM(blb2_p, g_blb2);

    const int T = 256;
    const int GRID_N = CDIV(NAUG, 128);
    cudaStream_t st = 0;

    // ---- setup (10 launches) ----
    k_build_edges<<<CDIV(MM, T), T, 0, st>>>(edge_index, edge_index + EE, batch);
    k_scanA<<<NB_SCAN, 256, 0, st>>>();
    k_scanB<<<1, 256, 0, st>>>();
    k_scanC<<<NB_SCAN, 256, 0, st>>>();
    k_scatter<<<CDIV(MM, T), T, 0, st>>>();
    k_misc<<<CDIV(2 * NN * D64, T), T, 0, st>>>(x, cond, batch);
    k_tail_csr<<<CDIV(NAUG * 32, T), T, 0, st>>>(edge_attr);
    k_eperm<<<CDIV(MM * 32, T), T, 0, st>>>(edge_attr);
    k_prep1<<<CDIV(LL * P1_PER, T), T, 0, st>>>(q_w, e_w, skip_w, lin_w, skip_b, lin_b);
    k_prep2<<<CDIV(LL * P2_PER, T), T, 0, st>>>(q_w, k_w, v_w, e_w, gen_w, gen_b,
                                                q_b, k_b, v_b, lin_w);

    // ---- layers (13 launches each) ----
    for (int i = 0; i < LL; i++) {
        const float* f1w = ff_w1 + (size_t)i * D64 * 4 * D64;
        const float* f1b = ff_b1 + (size_t)i * 4 * D64;
        const float* f2w = ff_w2 + (size_t)i * 4 * D64 * D64;
        const float* f2b = ff_b2 + (size_t)i * D64;
        float* wc2 = wcat2_p + (size_t)i * HD * 512;
        float* bc2 = bcat2_p + (size_t)i * 512;
        float* wl2 = wlin2_p + (size_t)i * 384 * D64;
        float* bl2 = blb2_p  + (size_t)i * D64;

        // LN1 -> hn + big[:, :64]
        k_ln_stats<<<CDIV(NAUG * 32, T), T, 0, st>>>(h_p);
        k_ln_final<<<1, GG, 0, st>>>();
        k_ln_apply2<<<CDIV(NAUG * D64, T), T, 0, st>>>(h_p);

        // gen_conv -> big[:, 64:128] (raw; GEMM folded into weights)
        k_gen<<<CDIV(NN * 32, T), T, 0, st>>>();
        k_gen_v<<<GG, T, 0, st>>>();

        // fused q|k|v|qp projection from [hn|geno]
        k_gemm_bf<0, 0, 0><<<dim3(GRID_N, 8), T, 0, st>>>(big_p, 384, wc2, 512, bc2,
                                                          qkvp_p, 512, NAUG, HD);

        // fused single-pass attention -> big[:, 128:256], big[:, 256:384]
        k_attn<<<CDIV(NN * 32, T), T, 0, st>>>();
        k_attn_v<<<GG, T, 0, st>>>();

        // lh = big @ wlin2 + blb2
        k_gemm_bf<0, 0, 0><<<dim3(GRID_N, 1), T, 0, st>>>(big_p, 384, wl2, D64, bl2,
                                                          lh_p, D64, NAUG, 384);

        // LN2 stats only; apply fused into ff1 loader
        k_ln_stats<<<CDIV(NAUG * 32, T), T, 0, st>>>(lh_p);
        k_ln_final<<<1, GG, 0, st>>>();

        // FF + residual (LN applied inline on A)
        k_gemm_bf<1, 0, 1><<<dim3(GRID_N, 4), T, 0, st>>>(lh_p, D64, f1w, 256, f1b,
                                                          ffh_p, 256, NAUG, D64);
        k_gemm_bf<0, 1, 0><<<dim3(GRID_N, 1), T, 0, st>>>(ffh_p, 256, f2w, D64, f2b,
                                                          h_p, D64, NAUG, 256);
    }

    // ---- outputs ----
    cudaMemcpyAsync(out, h_p, sizeof(float) * NN * D64, cudaMemcpyDeviceToDevice, st);
    k_glob_sum<<<CDIV(NN * D64, T), T, 0, st>>>(batch);
    k_glob_out<<<CDIV(GG * D64, T), T, 0, st>>>(out);
    k_ne_out<<<CDIV(NE_ * D64, T), T, 0, st>>>(ne_index, ne_index + NE_, out);
    k_cleanup<<<CDIV(GG * D64, T), T, 0, st>>>();
}

// round 10
// speedup vs baseline: 1.2160x; 1.0823x over previous
#include <cuda_runtime.h>
#include <cuda_bf16.h>
#include <math.h>
#include <stdint.h>

// Problem constants
#define D64   64
#define HH    2
#define HD    128
#define LL    3
#define NN    50000
#define GG    128
#define EE    600000
#define NE_   300000
#define NAUG  (NN + GG)          // 50128
#define M0    (EE + 2 * NN)      // 700000
#define MM    (M0 + NAUG)        // 750128
#define TAILR (MM - EE)          // 150128
#define NB_SCAN ((NAUG + 255) / 256)   // 196
#define NB_GEN  ((NN * 32 + 255) / 256)  // blocks for regular nodes (warp each)

#define CDIV(a, b) (((a) + (b) - 1) / (b))

// ---------------- device scratch (static, no allocs) ----------------
__device__ int    g_src[MM];
__device__ int    g_dst[MM];
__device__ int    g_deg[NAUG];
__device__ int    g_rowptr[NAUG + 1];
__device__ int    g_bsum[256];
__device__ int    g_fill[NAUG];
__device__ int    g_esrc[MM];
__device__ int    g_eid[MM];
__device__ float  g_eperm[(size_t)MM * D64];     // e_aug rows in CSR order
__device__ float  g_tail[(size_t)TAILR * D64];   // e_aug rows >= EE
__device__ float  g_h[NAUG * D64];
__device__ float  g_big[(size_t)NAUG * 384];     // [hn(64)|geno(64) | t(128) | we(128)]
__device__ float  g_qkvp[(size_t)NAUG * 512];    // [q | k | v | qp]
__device__ float  g_lh[NAUG * D64];
__device__ float  g_ffh[(size_t)NAUG * 256];
// per-layer precomputed weights
__device__ float  g_qpw[LL][HD * HD];
__device__ float  g_swlw[LL][HD * D64];
__device__ float  g_lw3[LL][HD * D64];
__device__ float  g_blb[LL][D64];
__device__ float  g_wcat2[LL][HD * 512];
__device__ float  g_bcat2[LL][512];
__device__ float  g_wlin2[LL][384 * D64];
__device__ float  g_blb2[LL][D64];
// LN / misc
__device__ float  g_cntn[GG];
__device__ double g_lsum[GG];
__device__ double g_lsumsq[GG];
__device__ float  g_mean[GG];
__device__ float  g_rstd[GG];
__device__ int    g_abatch[NAUG];
__device__ float  g_gsum[GG * D64];

// ---------------- setup kernels ----------------
__global__ void k_build_edges(const int* __restrict__ ei0, const int* __restrict__ ei1,
                              const int* __restrict__ batch) {
    int m = blockIdx.x * blockDim.x + threadIdx.x;
    if (m >= MM) return;
    int s, d;
    if (m < EE)               { s = ei0[m]; d = ei1[m]; }
    else if (m < EE + NN)     { int i = m - EE;          s = i;             d = batch[i] + NN; }
    else if (m < EE + 2 * NN) { int i = m - EE - NN;     s = batch[i] + NN; d = i; }
    else                      { int i = m - EE - 2 * NN; s = i;             d = i; }
    g_src[m] = s; g_dst[m] = d;
    atomicAdd(&g_deg[d], 1);
}

__global__ void k_scanA() {
    __shared__ int sh[256];
    int t = threadIdx.x;
    int i = blockIdx.x * 256 + t;
    int v = (i < NAUG) ? g_deg[i] : 0;
    sh[t] = v;
    __syncthreads();
    for (int off = 1; off < 256; off <<= 1) {
        int a = (t >= off) ? sh[t - off] : 0;
        __syncthreads();
        sh[t] += a;
        __syncthreads();
    }
    if (i < NAUG) g_rowptr[i] = sh[t] - v;
    if (t == 255) g_bsum[blockIdx.x] = sh[255];
}

__global__ void k_scanB() {
    __shared__ int sh[256];
    int t = threadIdx.x;
    int v = (t < NB_SCAN) ? g_bsum[t] : 0;
    sh[t] = v;
    __syncthreads();
    for (int off = 1; off < 256; off <<= 1) {
        int a = (t >= off) ? sh[t - off] : 0;
        __syncthreads();
        sh[t] += a;
        __syncthreads();
    }
    if (t < NB_SCAN) g_bsum[t] = sh[t] - v;
}

__global__ void k_scanC() {
    int i = blockIdx.x * 256 + threadIdx.x;
    if (i < NAUG) {
        int r = g_rowptr[i] + g_bsum[i >> 8];
        g_rowptr[i] = r;
        g_fill[i] = r;
        g_deg[i] = 0;                 // self-clean
    }
    if (i == 0) g_rowptr[NAUG] = MM;
}

__global__ void k_scatter() {
    int m = blockIdx.x * blockDim.x + threadIdx.x;
    if (m >= MM) return;
    int pos = atomicAdd(&g_fill[g_dst[m]], 1);
    g_esrc[pos] = g_src[m];
    g_eid[pos]  = m;
}

// fused misc setup: init h, e_p tail rows, abatch, cntn
__global__ void k_misc(const float* __restrict__ x, const float* __restrict__ cond,
                       const int* __restrict__ batch) {
    int idx = blockIdx.x * blockDim.x + threadIdx.x;
    if (idx < NAUG * D64)
        g_h[idx] = (idx < NN * D64) ? x[idx] : cond[idx - NN * D64];
    if (idx < 2 * NN * D64)
        g_tail[idx] = ((idx & 63) == 0) ? 1.f : 0.f;
    if (idx < NAUG)
        g_abatch[idx] = (idx < NN) ? batch[idx] : (idx - NN);
    if (idx < NN)
        atomicAdd(&g_cntn[batch[idx]], 1.f);
}

__global__ void k_tail_csr(const float* __restrict__ edge_attr) {
    int i = (blockIdx.x * blockDim.x + threadIdx.x) >> 5;
    int lane = threadIdx.x & 31;
    if (i >= NAUG) return;
    float2 acc = {0.f, 0.f};
    float cnt = 0.f;
    int e0 = g_rowptr[i], e1 = g_rowptr[i + 1];
    for (int e = e0; e < e1; e++) {
        int m = g_eid[e];
        if (m < EE) {
            float2 ev = ((const float2*)(edge_attr + (size_t)m * D64))[lane];
            acc.x += ev.x; acc.y += ev.y;
            cnt += 1.f;
        } else if (m < M0) {
            if (lane == 0) acc.x += 1.f;
            cnt += 1.f;
        }
    }
    float invc = 1.f / fmaxf(cnt, 1.f);
    float2 o = {acc.x * invc, acc.y * invc};
    ((float2*)(g_tail + (size_t)(2 * NN + i) * D64))[lane] = o;
}

__global__ void k_eperm(const float* __restrict__ edge_attr) {
    int gw = (blockIdx.x * blockDim.x + threadIdx.x) >> 5;
    int lane = threadIdx.x & 31;
    if (gw >= MM) return;
    int m = g_eid[gw];
    const float* ep = (m < EE) ? edge_attr + (size_t)m * D64
                               : g_tail + (size_t)(m - EE) * D64;
    float2 v = ((const float2*)ep)[lane];
    ((float2*)(g_eperm + (size_t)gw * D64))[lane] = v;
}

// ---------------- batched weight prep (all layers, 2 kernels) ----------------
#define P1_PER (128 * 128 + 128 * 64 + 128 * 64 + 64)   // 32832
__global__ void k_prep1(const float* __restrict__ qw_all, const float* __restrict__ ew_all,
                        const float* __restrict__ sw_all, const float* __restrict__ lw_all,
                        const float* __restrict__ sb_all, const float* __restrict__ lb_all) {
    int idx = blockIdx.x * blockDim.x + threadIdx.x;
    int l = idx / P1_PER, j = idx % P1_PER;
    if (l >= LL) return;
    const float* qw = qw_all + (size_t)l * HD * HD;
    const float* ew = ew_all + (size_t)l * D64 * HD;
    const float* sw = sw_all + (size_t)l * HD * HD;
    const float* lw = lw_all + (size_t)l * HD * D64;
    const float* sb = sb_all + (size_t)l * HD;
    const float* lb = lb_all + (size_t)l * D64;
    if (j < 128 * 128) {
        int xx = j >> 7, o = j & 127;
        int h = o >> 6, c = o & 63;
        float a = 0.f;
        for (int d = 0; d < 64; d++) a += qw[xx * HD + h * 64 + d] * ew[c * HD + h * 64 + d];
        g_qpw[l][j] = a;
    } else if (j < 128 * 128 + 128 * 64) {
        int jj = j - 128 * 128;
        int r = jj >> 6, u = jj & 63;
        float a = 0.f;
        for (int k2 = 0; k2 < 128; k2++) a += sw[r * HD + k2] * lw[k2 * D64 + u];
        g_swlw[l][jj] = a;
    } else if (j < 128 * 128 + 2 * 128 * 64) {
        int jj = j - 128 * 128 - 128 * 64;
        int r = jj >> 6, u = jj & 63;
        int h = r >> 6, c = r & 63;
        float a = 0.f;
        for (int o2 = 0; o2 < 64; o2++)
            a += ew[c * HD + h * 64 + o2] * lw[(h * 64 + o2) * D64 + u];
        g_lw3[l][jj] = a;
    } else {
        int o = j - 128 * 128 - 2 * 128 * 64;
        float a = lb[o];
        for (int k2 = 0; k2 < 128; k2++) a += sb[k2] * lw[k2 * D64 + o];
        g_blb[l][o] = a;
    }
}

__device__ __forceinline__ float wcat_row(const float* qw, const float* kw,
                                          const float* vw, const float* qpw,
                                          int r, int c) {
    if (c < 128) return qw[r * HD + c];
    if (c < 256) return kw[r * HD + c - 128];
    if (c < 384) return vw[r * HD + c - 256];
    return qpw[r * HD + c - 384];
}

#define P2_PER (128 * 512 + 384 * 64 + 512 + 64)   // 90688
__global__ void k_prep2(const float* __restrict__ qw_all, const float* __restrict__ kw_all,
                        const float* __restrict__ vw_all, const float* __restrict__ ew_all,
                        const float* __restrict__ gw_all, const float* __restrict__ gb_all,
                        const float* __restrict__ qb_all, const float* __restrict__ kb_all,
                        const float* __restrict__ vb_all, const float* __restrict__ lw_all) {
    int idx = blockIdx.x * blockDim.x + threadIdx.x;
    int l = idx / P2_PER, j = idx % P2_PER;
    if (l >= LL) return;
    const float* qw = qw_all + (size_t)l * HD * HD;
    const float* kw = kw_all + (size_t)l * HD * HD;
    const float* vw = vw_all + (size_t)l * HD * HD;
    const float* ew = ew_all + (size_t)l * D64 * HD;
    const float* gw = gw_all + (size_t)l * D64 * D64;
    const float* gb = gb_all + (size_t)l * D64;
    const float* qb = qb_all + (size_t)l * HD;
    const float* kb = kb_all + (size_t)l * HD;
    const float* vb = vb_all + (size_t)l * HD;
    const float* lw = lw_all + (size_t)l * HD * D64;
    const float* qpw = g_qpw[l];
    if (j < 128 * 512) {
        int r = j >> 9, c = j & 511;
        float v;
        if (r < 64) v = wcat_row(qw, kw, vw, qpw, r, c);
        else {
            int d = r - 64;
            float a = 0.f;
            for (int t = 0; t < 64; t++) a += gw[d * 64 + t] * wcat_row(qw, kw, vw, qpw, 64 + t, c);
            v = a;
        }
        g_wcat2[l][j] = v;
    } else if (j < 128 * 512 + 384 * 64) {
        int jj = j - 128 * 512;
        int r = jj >> 6, u = jj & 63;
        float v;
        if (r < 64) v = g_swlw[l][r * 64 + u];
        else if (r < 128) {
            int d = r - 64;
            float a = 0.f;
            for (int t = 0; t < 64; t++) a += gw[d * 64 + t] * g_swlw[l][(64 + t) * 64 + u];
            v = a;
        } else if (r < 256) v = lw[(size_t)(r - 128) * D64 + u];
        else v = g_lw3[l][(r - 256) * 64 + u];
        g_wlin2[l][jj] = v;
    } else if (j < 128 * 512 + 384 * 64 + 512) {
        int c = j - (128 * 512 + 384 * 64);
        float base;
        if (c < 128)      base = qb[c];
        else if (c < 256) base = kb[c - 128];
        else if (c < 384) base = vb[c - 256];
        else {
            int o = c - 384, h = o >> 6, cc = o & 63;
            float a = 0.f;
            for (int d = 0; d < 64; d++) a += qb[h * 64 + d] * ew[cc * HD + h * 64 + d];
            base = a;
        }
        float a = base;
        for (int t = 0; t < 64; t++) a += gb[t] * wcat_row(qw, kw, vw, qpw, 64 + t, c);
        g_bcat2[l][c] = a;
    } else {
        int u = j - (128 * 512 + 384 * 64 + 512);
        float a = g_blb[l][u];
        for (int t = 0; t < 64; t++) a += gb[t] * g_swlw[l][(64 + t) * 64 + u];
        g_blb2[l][u] = a;
    }
}

// ---------------- graph layernorm ----------------
__global__ void k_ln_stats(const float* __restrict__ X) {
    int i = (blockIdx.x * blockDim.x + threadIdx.x) >> 5;
    int lane = threadIdx.x & 31;
    if (i >= NAUG) return;
    float2 v = ((const float2*)(X + (size_t)i * D64))[lane];
    float s  = v.x + v.y;
    float ss = v.x * v.x + v.y * v.y;
#pragma unroll
    for (int off = 16; off; off >>= 1) {
        s  += __shfl_xor_sync(0xffffffffu, s, off);
        ss += __shfl_xor_sync(0xffffffffu, ss, off);
    }
    if (lane == 0) {
        int b = g_abatch[i];
        atomicAdd(&g_lsum[b], (double)s);
        atomicAdd(&g_lsumsq[b], (double)ss);
    }
}

__global__ void k_ln_final() {
    int g = threadIdx.x;
    if (g >= GG) return;
    double norm = (double)fmaxf(g_cntn[g] + 1.f, 1.f) * D64;
    double mean = g_lsum[g] / norm;
    double var  = g_lsumsq[g] / norm - mean * mean;
    g_mean[g] = (float)mean;
    g_rstd[g] = rsqrtf((float)var + 1e-5f);
    g_lsum[g] = 0.0;            // self-clean
    g_lsumsq[g] = 0.0;
}

// LN apply: h -> big[:, 0:64]
__global__ void k_ln_apply2(const float* __restrict__ X) {
    int idx = blockIdx.x * blockDim.x + threadIdx.x;
    if (idx >= NAUG * D64) return;
    int i = idx >> 6, d = idx & 63;
    int b = g_abatch[i];
    g_big[(size_t)i * 384 + d] = (X[idx] - g_mean[b]) * g_rstd[b];
}

// ---------------- gen_conv (merged regular+virtual), reads hn from big ----------------
__global__ void k_gen_all() {
    if (blockIdx.x < NB_GEN) {
        int i = (blockIdx.x * blockDim.x + threadIdx.x) >> 5;
        int lane = threadIdx.x & 31;
        if (i >= NN) return;
        float2 acc = {0.f, 0.f};
        int e0 = g_rowptr[i], e1 = g_rowptr[i + 1];
        for (int e = e0; e < e1; e++) {
            int s = g_esrc[e];
            float2 ev = ((const float2*)(g_eperm + (size_t)e * D64))[lane];
            float2 hv = ((const float2*)(g_big + (size_t)s * 384))[lane];
            acc.x += fmaxf(hv.x + ev.x, 0.f) + 1e-7f;
            acc.y += fmaxf(hv.y + ev.y, 0.f) + 1e-7f;
        }
        float2 hi = ((const float2*)(g_big + (size_t)i * 384))[lane];
        float2 o = {acc.x + hi.x, acc.y + hi.y};
        ((float2*)(g_big + (size_t)i * 384 + 64))[lane] = o;
    } else {
        __shared__ float sa[64];
        int i = NN + (blockIdx.x - NB_GEN);
        int tid = threadIdx.x, lane = tid & 31, wid = tid >> 5;
        if (tid < 64) sa[tid] = 0.f;
        __syncthreads();
        int e0 = g_rowptr[i], e1 = g_rowptr[i + 1];
        float2 acc = {0.f, 0.f};
        for (int e = e0 + wid; e < e1; e += 8) {
            int s = g_esrc[e];
            float2 ev = ((const float2*)(g_eperm + (size_t)e * D64))[lane];
            float2 hv = ((const float2*)(g_big + (size_t)s * 384))[lane];
            acc.x += fmaxf(hv.x + ev.x, 0.f) + 1e-7f;
            acc.y += fmaxf(hv.y + ev.y, 0.f) + 1e-7f;
        }
        atomicAdd(&sa[2 * lane],     acc.x);
        atomicAdd(&sa[2 * lane + 1], acc.y);
        __syncthreads();
        if (tid < 64) g_big[(size_t)i * 384 + 64 + tid] = sa[tid] + g_big[(size_t)i * 384 + tid];
    }
}

// ---------------- fused single-pass attention (merged regular+virtual) ----------------
__global__ void k_attn_all() {
    if (blockIdx.x < NB_GEN) {
        int i = (blockIdx.x * blockDim.x + threadIdx.x) >> 5;
        int lane = threadIdx.x & 31;
        if (i >= NN) return;
        int el = lane & 15;
        float4 q4  = *(const float4*)(g_qkvp + (size_t)i * 512 + 4 * lane);
        float4 qp4 = *(const float4*)(g_qkvp + (size_t)i * 512 + 384 + 4 * lane);
        int e0 = g_rowptr[i], e1 = g_rowptr[i + 1];
        float mx = -INFINITY, sum = 0.f;
        float4 vacc = {0.f, 0.f, 0.f, 0.f};
        float4 eacc = {0.f, 0.f, 0.f, 0.f};
        for (int e = e0; e < e1; e++) {
            int s = g_esrc[e];
            const float* ep = g_eperm + (size_t)e * D64;
            float4 k4 = *(const float4*)(g_qkvp + (size_t)s * 512 + 128 + 4 * lane);
            float4 e4 = *(const float4*)(ep + 4 * el);
            float p = q4.x * k4.x + q4.y * k4.y + q4.z * k4.z + q4.w * k4.w
                    + qp4.x * e4.x + qp4.y * e4.y + qp4.z * e4.z + qp4.w * e4.w;
            p += __shfl_xor_sync(0xffffffffu, p, 1);
            p += __shfl_xor_sync(0xffffffffu, p, 2);
            p += __shfl_xor_sync(0xffffffffu, p, 4);
            p += __shfl_xor_sync(0xffffffffu, p, 8);
            float a = p * 0.125f;
            if (a > mx) {
                float sc = expf(mx - a);
                sum *= sc;
                vacc.x *= sc; vacc.y *= sc; vacc.z *= sc; vacc.w *= sc;
                eacc.x *= sc; eacc.y *= sc; eacc.z *= sc; eacc.w *= sc;
                mx = a;
            }
            float w = expf(a - mx);
            sum += w;
            float4 v4 = *(const float4*)(g_qkvp + (size_t)s * 512 + 256 + 4 * lane);
            vacc.x += w * v4.x; vacc.y += w * v4.y; vacc.z += w * v4.z; vacc.w += w * v4.w;
            eacc.x += w * e4.x; eacc.y += w * e4.y; eacc.z += w * e4.z; eacc.w += w * e4.w;
        }
        float inv = 1.f / (sum + 1e-16f);
        float4 to = {vacc.x * inv, vacc.y * inv, vacc.z * inv, vacc.w * inv};
        float4 wo = {eacc.x * inv, eacc.y * inv, eacc.z * inv, eacc.w * inv};
        *(float4*)(g_big + (size_t)i * 384 + 128 + 4 * lane) = to;
        *(float4*)(g_big + (size_t)i * 384 + 256 + 4 * lane) = wo;
    } else {
        __shared__ float sv[128];
        __shared__ float se[128];
        __shared__ float ssg[2];
        __shared__ float swmx[16];
        __shared__ float gmx[2];
        int i = NN + (blockIdx.x - NB_GEN);
        int tid = threadIdx.x, lane = tid & 31, wid = tid >> 5;
        int el = lane & 15;
        int hh = lane >> 4;
        if (tid < 128) { sv[tid] = 0.f; se[tid] = 0.f; }
        if (tid < 2) ssg[tid] = 0.f;
        __syncthreads();
        float4 q4  = *(const float4*)(g_qkvp + (size_t)i * 512 + 4 * lane);
        float4 qp4 = *(const float4*)(g_qkvp + (size_t)i * 512 + 384 + 4 * lane);
        int e0 = g_rowptr[i], e1 = g_rowptr[i + 1];
        float mx = -INFINITY, sum = 0.f;
        float4 vacc = {0.f, 0.f, 0.f, 0.f};
        float4 eacc = {0.f, 0.f, 0.f, 0.f};
        for (int e = e0 + wid; e < e1; e += 8) {
            int s = g_esrc[e];
            const float* ep = g_eperm + (size_t)e * D64;
            float4 k4 = *(const float4*)(g_qkvp + (size_t)s * 512 + 128 + 4 * lane);
            float4 e4 = *(const float4*)(ep + 4 * el);
            float p = q4.x * k4.x + q4.y * k4.y + q4.z * k4.z + q4.w * k4.w
                    + qp4.x * e4.x + qp4.y * e4.y + qp4.z * e4.z + qp4.w * e4.w;
            p += __shfl_xor_sync(0xffffffffu, p, 1);
            p += __shfl_xor_sync(0xffffffffu, p, 2);
            p += __shfl_xor_sync(0xffffffffu, p, 4);
            p += __shfl_xor_sync(0xffffffffu, p, 8);
            float a = p * 0.125f;
            if (a > mx) {
                float sc = expf(mx - a);
                sum *= sc;
                vacc.x *= sc; vacc.y *= sc; vacc.z *= sc; vacc.w *= sc;
                eacc.x *= sc; eacc.y *= sc; eacc.z *= sc; eacc.w *= sc;
                mx = a;
            }
            float w = expf(a - mx);
            sum += w;
            float4 v4 = *(const float4*)(g_qkvp + (size_t)s * 512 + 256 + 4 * lane);
            vacc.x += w * v4.x; vacc.y += w * v4.y; vacc.z += w * v4.z; vacc.w += w * v4.w;
            eacc.x += w * e4.x; eacc.y += w * e4.y; eacc.z += w * e4.z; eacc.w += w * e4.w;
        }
        if (el == 0) swmx[wid * 2 + hh] = mx;
        __syncthreads();
        if (tid < 2) {
            float m = -INFINITY;
#pragma unroll
            for (int w = 0; w < 8; w++) m = fmaxf(m, swmx[w * 2 + tid]);
            gmx[tid] = m;
        }
        __syncthreads();
        float sc = expf(mx - gmx[hh]);
        atomicAdd(&sv[4 * lane],     vacc.x * sc); atomicAdd(&sv[4 * lane + 1], vacc.y * sc);
        atomicAdd(&sv[4 * lane + 2], vacc.z * sc); atomicAdd(&sv[4 * lane + 3], vacc.w * sc);
        atomicAdd(&se[4 * lane],     eacc.x * sc); atomicAdd(&se[4 * lane + 1], eacc.y * sc);
        atomicAdd(&se[4 * lane + 2], eacc.z * sc); atomicAdd(&se[4 * lane + 3], eacc.w * sc);
        if (el == 0) atomicAdd(&ssg[hh], sum * sc);
        __syncthreads();
        if (tid < 128) {
            float inv = 1.f / (ssg[tid >> 6] + 1e-16f);
            g_big[(size_t)i * 384 + 128 + tid] = sv[tid] * inv;
            g_big[(size_t)i * 384 + 256 + tid] = se[tid] * inv;
        }
    }
}

// ---------------- 3xBF16 tensor-core GEMM (LN-on-A and row-stats options) ----------------
__device__ __forceinline__ void mma16(float* c, uint32_t a0, uint32_t a1, uint32_t a2,
                                      uint32_t a3, uint32_t b0, uint32_t b1) {
    asm volatile(
        "mma.sync.aligned.m16n8k16.row.col.f32.bf16.bf16.f32 "
        "{%0,%1,%2,%3}, {%4,%5,%6,%7}, {%8,%9}, {%0,%1,%2,%3};"
        : "+f"(c[0]), "+f"(c[1]), "+f"(c[2]), "+f"(c[3])
        : "r"(a0), "r"(a1), "r"(a2), "r"(a3), "r"(b0), "r"(b1));
}

// STATS=1 requires OUT tile == full row width (gridDim.y == 1, ldc == 64).
template <int ACT, int ACCUM, int LNA, int STATS>
__global__ __launch_bounds__(256) void k_gemm_bf(
        const float* __restrict__ A, int lda,
        const float* __restrict__ W, int wld,
        const float* __restrict__ bias, float* __restrict__ C,
        int ldc, int rows, int K) {
    __shared__ __align__(16) __nv_bfloat16 Ah[128][40];
    __shared__ __align__(16) __nv_bfloat16 Al[128][40];
    __shared__ __align__(16) __nv_bfloat16 Wh[64][40];
    __shared__ __align__(16) __nv_bfloat16 Wl[64][40];
    __shared__ float sS[128], sSS[128];
    const int tid = threadIdx.x, lane = tid & 31, warp = tid >> 5;
    const int warpM = warp & 3, warpN = warp >> 2;
    const int gid = lane >> 2, tig = lane & 3;
    const int r0 = blockIdx.x * 128, col0 = blockIdx.y * 64;
    if (STATS && tid < 128) { sS[tid] = 0.f; sSS[tid] = 0.f; }
    float acc[2][4][4];
#pragma unroll
    for (int mt = 0; mt < 2; mt++)
#pragma unroll
        for (int nt = 0; nt < 4; nt++)
#pragma unroll
            for (int r = 0; r < 4; r++) acc[mt][nt][r] = 0.f;

    for (int k0 = 0; k0 < K; k0 += 32) {
#pragma unroll
        for (int t = 0; t < 4; t++) {
            int li = tid + t * 256;
            int r = li >> 3, kq = li & 7;
            int row = r0 + r;
            float4 av = make_float4(0.f, 0.f, 0.f, 0.f);
            if (row < rows) {
                av = *(const float4*)(A + (size_t)row * lda + k0 + kq * 4);
                if (LNA) {
                    int b = g_abatch[row];
                    float mu = g_mean[b], rs = g_rstd[b];
                    av.x = (av.x - mu) * rs; av.y = (av.y - mu) * rs;
                    av.z = (av.z - mu) * rs; av.w = (av.w - mu) * rs;
                }
            }
            __nv_bfloat16 h0 = __float2bfloat16_rn(av.x);
            __nv_bfloat16 h1 = __float2bfloat16_rn(av.y);
            __nv_bfloat16 h2 = __float2bfloat16_rn(av.z);
            __nv_bfloat16 h3 = __float2bfloat16_rn(av.w);
            Ah[r][kq * 4 + 0] = h0; Ah[r][kq * 4 + 1] = h1;
            Ah[r][kq * 4 + 2] = h2; Ah[r][kq * 4 + 3] = h3;
            Al[r][kq * 4 + 0] = __float2bfloat16_rn(av.x - __bfloat162float(h0));
            Al[r][kq * 4 + 1] = __float2bfloat16_rn(av.y - __bfloat162float(h1));
            Al[r][kq * 4 + 2] = __float2bfloat16_rn(av.z - __bfloat162float(h2));
            Al[r][kq * 4 + 3] = __float2bfloat16_rn(av.w - __bfloat162float(h3));
        }
#pragma unroll
        for (int t = 0; t < 2; t++) {
            int li = tid + t * 256;
            int kk = li >> 4, oq = li & 15;
            float4 wv = *(const float4*)(W + (size_t)(k0 + kk) * wld + col0 + oq * 4);
            __nv_bfloat16 h0 = __float2bfloat16_rn(wv.x);
            __nv_bfloat16 h1 = __float2bfloat16_rn(wv.y);
            __nv_bfloat16 h2 = __float2bfloat16_rn(wv.z);
            __nv_bfloat16 h3 = __float2bfloat16_rn(wv.w);
            Wh[oq * 4 + 0][kk] = h0; Wh[oq * 4 + 1][kk] = h1;
            Wh[oq * 4 + 2][kk] = h2; Wh[oq * 4 + 3][kk] = h3;
            Wl[oq * 4 + 0][kk] = __float2bfloat16_rn(wv.x - __bfloat162float(h0));
            Wl[oq * 4 + 1][kk] = __float2bfloat16_rn(wv.y - __bfloat162float(h1));
            Wl[oq * 4 + 2][kk] = __float2bfloat16_rn(wv.z - __bfloat162float(h2));
            Wl[oq * 4 + 3][kk] = __float2bfloat16_rn(wv.w - __bfloat162float(h3));
        }
        __syncthreads();
#pragma unroll
        for (int ks = 0; ks < 2; ks++) {
            int kb = ks * 16;
            uint32_t ah[2][4], al[2][4];
#pragma unroll
            for (int mt = 0; mt < 2; mt++) {
                int ar = warpM * 32 + mt * 16 + gid;
                ah[mt][0] = *(const uint32_t*)&Ah[ar][kb + 2 * tig];
                ah[mt][1] = *(const uint32_t*)&Ah[ar + 8][kb + 2 * tig];
                ah[mt][2] = *(const uint32_t*)&Ah[ar][kb + 2 * tig + 8];
                ah[mt][3] = *(const uint32_t*)&Ah[ar + 8][kb + 2 * tig + 8];
                al[mt][0] = *(const uint32_t*)&Al[ar][kb + 2 * tig];
                al[mt][1] = *(const uint32_t*)&Al[ar + 8][kb + 2 * tig];
                al[mt][2] = *(const uint32_t*)&Al[ar][kb + 2 * tig + 8];
                al[mt][3] = *(const uint32_t*)&Al[ar + 8][kb + 2 * tig + 8];
            }
            uint32_t bh[4][2], bl[4][2];
#pragma unroll
            for (int nt = 0; nt < 4; nt++) {
                int bc = warpN * 32 + nt * 8 + gid;
                bh[nt][0] = *(const uint32_t*)&Wh[bc][kb + 2 * tig];
                bh[nt][1] = *(const uint32_t*)&Wh[bc][kb + 2 * tig + 8];
                bl[nt][0] = *(const uint32_t*)&Wl[bc][kb + 2 * tig];
                bl[nt][1] = *(const uint32_t*)&Wl[bc][kb + 2 * tig + 8];
            }
#pragma unroll
            for (int mt = 0; mt < 2; mt++)
#pragma unroll
                for (int nt = 0; nt < 4; nt++) {
                    mma16(acc[mt][nt], ah[mt][0], ah[mt][1], ah[mt][2], ah[mt][3],
                          bl[nt][0], bl[nt][1]);
                    mma16(acc[mt][nt], al[mt][0], al[mt][1], al[mt][2], al[mt][3],
                          bh[nt][0], bh[nt][1]);
                    mma16(acc[mt][nt], ah[mt][0], ah[mt][1], ah[mt][2], ah[mt][3],
                          bh[nt][0], bh[nt][1]);
                }
        }
        __syncthreads();
    }
#pragma unroll
    for (int mt = 0; mt < 2; mt++) {
        int rl = r0 + warpM * 32 + mt * 16 + gid;
#pragma unroll
        for (int half = 0; half < 2; half++) {
            int row = rl + half * 8;
            if (row >= rows) continue;
            float s = 0.f, ss = 0.f;
#pragma unroll
            for (int nt = 0; nt < 4; nt++) {
                int col = col0 + warpN * 32 + nt * 8 + tig * 2;
                float v0 = acc[mt][nt][half * 2 + 0];
                float v1 = acc[mt][nt][half * 2 + 1];
                if (bias) { v0 += bias[col]; v1 += bias[col + 1]; }
                if (ACT == 1) {
                    v0 = (v0 > 0.f) ? v0 : 0.01f * v0;
                    v1 = (v1 > 0.f) ? v1 : 0.01f * v1;
                }
                float2* cp = (float2*)(C + (size_t)row * ldc + col);
                if (ACCUM) { float2 o = *cp; v0 += o.x; v1 += o.y; }
                *cp = make_float2(v0, v1);
                if (STATS) { s += v0 + v1; ss += v0 * v0 + v1 * v1; }
            }
            if (STATS) {
                int rloc = row - r0;
                atomicAdd(&sS[rloc], s);
                atomicAdd(&sSS[rloc], ss);
            }
        }
    }
    if (STATS) {
        __syncthreads();
        if (tid < 128) {
            int row = r0 + tid;
            if (row < rows) {
                int b = g_abatch[row];
                atomicAdd(&g_lsum[b], (double)sS[tid]);
                atomicAdd(&g_lsumsq[b], (double)sSS[tid]);
            }
        }
    }
}

// ---------------- outputs ----------------
__global__ void k_out1(const int* __restrict__ batch, const int* __restrict__ ne0,
                       const int* __restrict__ ne1, float* __restrict__ out) {
    int idx = blockIdx.x * blockDim.x + threadIdx.x;
    if (idx < NN * D64)
        atomicAdd(&g_gsum[batch[idx >> 6] * D64 + (idx & 63)], g_h[idx]);
    if (idx < NE_ * D64) {
        int j = idx >> 6, d = idx & 63;
        out[(NN + GG) * D64 + idx] = g_h[ne0[j] * D64 + d] + g_h[ne1[j] * D64 + d];
    }
}

__global__ void k_glob_out(float* __restrict__ out) {
    int idx = blockIdx.x * blockDim.x + threadIdx.x;
    if (idx >= GG * D64) return;
    int g = idx >> 6;
    out[NN * D64 + idx] = g_gsum[idx] / fmaxf(g_cntn[g], 1.f) + g_h[NN * D64 + idx];
}

__global__ void k_cleanup() {
    int idx = blockIdx.x * blockDim.x + threadIdx.x;
    if (idx < GG * D64) g_gsum[idx] = 0.f;
    if (idx < GG) { g_cntn[idx] = 0.f; g_lsum[idx] = 0.0; g_lsumsq[idx] = 0.0; }
}

// ---------------- host launcher ----------------
#define GETSYM(ptr, sym) do { void* _p; cudaGetSymbolAddress(&_p, sym); ptr = (decltype(ptr))_p; } while (0)

extern "C" void kernel_launch(void* const* d_in, const int* in_sizes, int n_in,
                              void* d_out, int out_size) {
    const float* x          = (const float*)d_in[0];
    const float* cond       = (const float*)d_in[1];
    const float* edge_attr  = (const float*)d_in[2];
    const int*   edge_index = (const int*)d_in[3];
    const int*   ne_index   = (const int*)d_in[4];
    const int*   batch      = (const int*)d_in[5];
    const float* gen_w  = (const float*)d_in[6];
    const float* gen_b  = (const float*)d_in[7];
    const float* q_w    = (const float*)d_in[8];
    const float* q_b    = (const float*)d_in[9];
    const float* k_w    = (const float*)d_in[10];
    const float* k_b    = (const float*)d_in[11];
    const float* v_w    = (const float*)d_in[12];
    const float* v_b    = (const float*)d_in[13];
    const float* e_w    = (const float*)d_in[14];
    const float* skip_w = (const float*)d_in[15];
    const float* skip_b = (const float*)d_in[16];
    const float* lin_w  = (const float*)d_in[17];
    const float* lin_b  = (const float*)d_in[18];
    const float* ff_w1  = (const float*)d_in[19];
    const float* ff_b1  = (const float*)d_in[20];
    const float* ff_w2  = (const float*)d_in[21];
    const float* ff_b2  = (const float*)d_in[22];
    float* out = (float*)d_out;

    float *h_p, *big_p, *qkvp_p, *lh_p, *ffh_p;
    float *wcat2_p, *bcat2_p, *wlin2_p, *blb2_p;
    GETSYM(h_p, g_h);       GETSYM(big_p, g_big);   GETSYM(qkvp_p, g_qkvp);
    GETSYM(lh_p, g_lh);     GETSYM(ffh_p, g_ffh);
    GETSYM(wcat2_p, g_wcat2); GETSYM(bcat2_p, g_bcat2);
    GETSYM(wlin2_p, g_wlin2); GETSYM(blb2_p, g_blb2);

    const int T = 256;
    const int GRID_N = CDIV(NAUG, 128);
    cudaStream_t st = 0;

    // ---- setup (11 launches) ----
    k_build_edges<<<CDIV(MM, T), T, 0, st>>>(edge_index, edge_index + EE, batch);
    k_scanA<<<NB_SCAN, 256, 0, st>>>();
    k_scanB<<<1, 256, 0, st>>>();
    k_scanC<<<NB_SCAN, 256, 0, st>>>();
    k_scatter<<<CDIV(MM, T), T, 0, st>>>();
    k_misc<<<CDIV(2 * NN * D64, T), T, 0, st>>>(x, cond, batch);
    k_tail_csr<<<CDIV(NAUG * 32, T), T, 0, st>>>(edge_attr);
    k_eperm<<<CDIV(MM * 32, T), T, 0, st>>>(edge_attr);
    k_prep1<<<CDIV(LL * P1_PER, T), T, 0, st>>>(q_w, e_w, skip_w, lin_w, skip_b, lin_b);
    k_prep2<<<CDIV(LL * P2_PER, T), T, 0, st>>>(q_w, k_w, v_w, e_w, gen_w, gen_b,
                                                q_b, k_b, v_b, lin_w);
    k_ln_stats<<<CDIV(NAUG * 32, T), T, 0, st>>>(h_p);   // layer-0 LN1 stats

    // ---- layers (9 launches each) ----
    for (int i = 0; i < LL; i++) {
        const float* f1w = ff_w1 + (size_t)i * D64 * 4 * D64;
        const float* f1b = ff_b1 + (size_t)i * 4 * D64;
        const float* f2w = ff_w2 + (size_t)i * 4 * D64 * D64;
        const float* f2b = ff_b2 + (size_t)i * D64;
        float* wc2 = wcat2_p + (size_t)i * HD * 512;
        float* bc2 = bcat2_p + (size_t)i * 512;
        float* wl2 = wlin2_p + (size_t)i * 384 * D64;
        float* bl2 = blb2_p  + (size_t)i * D64;

        k_ln_final<<<1, GG, 0, st>>>();
        k_ln_apply2<<<CDIV(NAUG * D64, T), T, 0, st>>>(h_p);

        k_gen_all<<<NB_GEN + GG, T, 0, st>>>();

        k_gemm_bf<0, 0, 0, 0><<<dim3(GRID_N, 8), T, 0, st>>>(big_p, 384, wc2, 512, bc2,
                                                             qkvp_p, 512, NAUG, HD);

        k_attn_all<<<NB_GEN + GG, T, 0, st>>>();

        // lh = big @ wlin2 + blb2  (+ LN2 stats in epilogue)
        k_gemm_bf<0, 0, 0, 1><<<dim3(GRID_N, 1), T, 0, st>>>(big_p, 384, wl2, D64, bl2,
                                                             lh_p, D64, NAUG, 384);
        k_ln_final<<<1, GG, 0, st>>>();

        // FF + residual (LN applied inline on A; ff2 epilogue -> next-layer LN1 stats)
        k_gemm_bf<1, 0, 1, 0><<<dim3(GRID_N, 4), T, 0, st>>>(lh_p, D64, f1w, 256, f1b,
                                                             ffh_p, 256, NAUG, D64);
        k_gemm_bf<0, 1, 0, 1><<<dim3(GRID_N, 1), T, 0, st>>>(ffh_p, 256, f2w, D64, f2b,
                                                             h_p, D64, NAUG, 256);
    }

    // ---- outputs ----
    cudaMemcpyAsync(out, h_p, sizeof(float) * NN * D64, cudaMemcpyDeviceToDevice, st);
    k_out1<<<CDIV(NE_ * D64, T), T, 0, st>>>(batch, ne_index, ne_index + NE_, out);
    k_glob_out<<<CDIV(GG * D64, T), T, 0, st>>>(out);
    k_cleanup<<<CDIV(GG * D64, T), T, 0, st>>>();
}